// round 1
// baseline (speedup 1.0000x reference)
#include <cuda_runtime.h>
#include <math.h>

#define NPTS 8192
#define DIM 256

// ---------------- static device scratch (no allocation allowed) ----------------
__device__ float d_wc[DIM];
__device__ float d_an[(size_t)NPTS * DIM];
__device__ float d_bn[(size_t)NPTS * DIM];
__device__ float d_Gxy[(size_t)NPTS * NPTS];   // an . bn^T
__device__ float d_Gyx[(size_t)NPTS * NPTS];   // transpose of Gxy
__device__ float d_Gxx[(size_t)NPTS * NPTS];   // an . an^T
__device__ float d_Gyy[(size_t)NPTS * NPTS];   // bn . bn^T
__device__ float d_f[2][NPTS];
__device__ float d_g[2][NPTS];
__device__ float d_fxx[2][NPTS];
__device__ float d_gyy[2][NPTS];
__device__ float d_ffin[NPTS], d_gfin[NPTS], d_xfin[NPTS], d_yfin[NPTS];

// ---------------- prep: clip+renormalize w ----------------
__global__ void wprep_kernel(const float* __restrict__ w) {
    __shared__ float sh[DIM];
    int t = threadIdx.x;
    float c = fminf(fmaxf(w[t], 0.0f), 2.0f);
    sh[t] = c;
    __syncthreads();
    for (int off = DIM / 2; off > 0; off >>= 1) {
        if (t < off) sh[t] += sh[t + off];
        __syncthreads();
    }
    float S = sh[0];                 // sum of clipped w; mean = S/256
    d_wc[t] = c * ((float)DIM / S);  // c / mean
}

// ---------------- prep: row-normalize an (with wc) and bn ----------------
__global__ void rownorm_kernel(const float* __restrict__ x1, const float* __restrict__ x2) {
    __shared__ float sh[DIM];
    int b = blockIdx.x, t = threadIdx.x;
    float v;
    if (b < NPTS) v = d_wc[t] * x1[(size_t)b * DIM + t];
    else          v = x2[(size_t)(b - NPTS) * DIM + t];
    sh[t] = v * v;
    __syncthreads();
    for (int off = DIM / 2; off > 0; off >>= 1) {
        if (t < off) sh[t] += sh[t + off];
        __syncthreads();
    }
    float inv = 1.0f / (sqrtf(sh[0]) + 1e-12f);
    if (b < NPTS) d_an[(size_t)b * DIM + t] = v * inv;
    else          d_bn[(size_t)(b - NPTS) * DIM + t] = v * inv;
}

// ---------------- zero potentials (deterministic per launch) ----------------
__global__ void zero_kernel() {
    int i = blockIdx.x * blockDim.x + threadIdx.x;
    if (i < NPTS) {
        d_f[0][i] = 0.0f; d_g[0][i] = 0.0f;
        d_fxx[0][i] = 0.0f; d_gyy[0][i] = 0.0f;
    }
}

// ---------------- GEMM: C = A * B^T  (A,B: NPTS x DIM row-major) ----------------
// 128x128 tiles, 256 threads, 8x8 per thread. Optional transposed write (CT)
// and symmetric mode (compute lower triangle, mirror to upper).
__global__ void __launch_bounds__(256) gemm_nt(const float* __restrict__ A,
                                               const float* __restrict__ B,
                                               float* __restrict__ C,
                                               float* __restrict__ CT,
                                               int sym) {
    int btx = blockIdx.x, bty = blockIdx.y;
    if (sym && btx > bty) return;

    __shared__ float As[16][128];
    __shared__ float Bs[16][128];

    int tid = threadIdx.x;
    int tx = tid & 15, ty = tid >> 4;
    int rowBase = bty * 128, colBase = btx * 128;

    float acc[8][8];
#pragma unroll
    for (int r = 0; r < 8; ++r)
#pragma unroll
        for (int c = 0; c < 8; ++c) acc[r][c] = 0.0f;

    for (int kt = 0; kt < DIM; kt += 16) {
#pragma unroll
        for (int q = 0; q < 2; ++q) {
            int li = q * 256 + tid;        // 0..511 float4 slots
            int r  = li >> 2;              // 0..127 tile row
            int k4 = (li & 3) * 4;         // 0,4,8,12
            float4 va = *(const float4*)(A + (size_t)(rowBase + r) * DIM + kt + k4);
            As[k4 + 0][r] = va.x; As[k4 + 1][r] = va.y;
            As[k4 + 2][r] = va.z; As[k4 + 3][r] = va.w;
            float4 vb = *(const float4*)(B + (size_t)(colBase + r) * DIM + kt + k4);
            Bs[k4 + 0][r] = vb.x; Bs[k4 + 1][r] = vb.y;
            Bs[k4 + 2][r] = vb.z; Bs[k4 + 3][r] = vb.w;
        }
        __syncthreads();
#pragma unroll
        for (int kk = 0; kk < 16; ++kk) {
            float a[8], b[8];
            *(float4*)(a)     = *(const float4*)&As[kk][ty * 8];
            *(float4*)(a + 4) = *(const float4*)&As[kk][ty * 8 + 4];
            *(float4*)(b)     = *(const float4*)&Bs[kk][tx * 8];
            *(float4*)(b + 4) = *(const float4*)&Bs[kk][tx * 8 + 4];
#pragma unroll
            for (int r = 0; r < 8; ++r)
#pragma unroll
                for (int c = 0; c < 8; ++c)
                    acc[r][c] = fmaf(a[r], b[c], acc[r][c]);
        }
        __syncthreads();
    }

    // normal epilogue
#pragma unroll
    for (int r = 0; r < 8; ++r) {
        float4 v0 = make_float4(acc[r][0], acc[r][1], acc[r][2], acc[r][3]);
        float4 v1 = make_float4(acc[r][4], acc[r][5], acc[r][6], acc[r][7]);
        size_t base = (size_t)(rowBase + ty * 8 + r) * NPTS + colBase + tx * 8;
        *(float4*)(C + base)     = v0;
        *(float4*)(C + base + 4) = v1;
    }
    // transposed epilogue (for Gyx, or mirrored block for symmetric matrices)
    if (CT != nullptr && !(sym && btx == bty)) {
#pragma unroll
        for (int c = 0; c < 8; ++c) {
            float4 v0 = make_float4(acc[0][c], acc[1][c], acc[2][c], acc[3][c]);
            float4 v1 = make_float4(acc[4][c], acc[5][c], acc[6][c], acc[7][c]);
            size_t base = (size_t)(colBase + tx * 8 + c) * NPTS + rowBase + ty * 8;
            *(float4*)(CT + base)     = v0;
            *(float4*)(CT + base + 4) = v1;
        }
    }
}

// ---------------- softmin: out_i = -eps*(log_w + LSE_j((pot_j + G_ij - 1)/eps)) ----------------
// avg=1: out_i = 0.5*(oldpot_i + softmin_i)
__global__ void __launch_bounds__(256) softmin_kernel(const float* __restrict__ G,
                                                      const float* __restrict__ pot,
                                                      const float* __restrict__ oldpot,
                                                      float* __restrict__ out,
                                                      float eps, int avg) {
    __shared__ float sp[NPTS];     // (pot_j - 1) / eps
    __shared__ float red_m[256];
    __shared__ float red_s[256];

    const float L2E = 1.4426950408889634f;
    int row = blockIdx.x;
    int tid = threadIdx.x;
    float inv_eps = 1.0f / eps;

    for (int j = tid; j < NPTS; j += 256)
        sp[j] = (pot[j] - 1.0f) * inv_eps;
    __syncthreads();

    const float4* Grow = (const float4*)(G + (size_t)row * NPTS);
    float m = -INFINITY, s = 0.0f;

#pragma unroll
    for (int it = 0; it < 8; ++it) {
        int j4 = tid + it * 256;
        float4 gv = Grow[j4];
        int j = j4 * 4;
        float v0 = fmaf(gv.x, inv_eps, sp[j + 0]);
        float v1 = fmaf(gv.y, inv_eps, sp[j + 1]);
        float v2 = fmaf(gv.z, inv_eps, sp[j + 2]);
        float v3 = fmaf(gv.w, inv_eps, sp[j + 3]);
#define ONLINE(v)                                              \
        if ((v) <= m) { s += exp2f(((v) - m) * L2E); }         \
        else { s = fmaf(s, exp2f((m - (v)) * L2E), 1.0f); m = (v); }
        ONLINE(v0) ONLINE(v1) ONLINE(v2) ONLINE(v3)
#undef ONLINE
    }

    red_m[tid] = m; red_s[tid] = s;
    __syncthreads();
    for (int off = 128; off > 0; off >>= 1) {
        if (tid < off) {
            float m2 = red_m[tid + off], s2 = red_s[tid + off];
            float m1 = red_m[tid],       s1 = red_s[tid];
            float mm = fmaxf(m1, m2);
            red_s[tid] = s1 * exp2f((m1 - mm) * L2E) + s2 * exp2f((m2 - mm) * L2E);
            red_m[tid] = mm;
        }
        __syncthreads();
    }
    if (tid == 0) {
        const float LOGW = -9.010913347279288f;  // -log(8192)
        float lse = red_m[0] + logf(red_s[0]);
        float r = -eps * (LOGW + lse);
        if (avg) r = 0.5f * (oldpot[row] + r);
        out[row] = r;
    }
}

// ---------------- final reduction ----------------
__global__ void final_reduce(float* __restrict__ out) {
    __shared__ float sh[1024];
    int t = threadIdx.x;
    float s = 0.0f;
    for (int i = t; i < NPTS; i += 1024)
        s += (d_ffin[i] - d_xfin[i]) + (d_gfin[i] - d_yfin[i]);
    sh[t] = s;
    __syncthreads();
    for (int off = 512; off > 0; off >>= 1) {
        if (t < off) sh[t] += sh[t + off];
        __syncthreads();
    }
    if (t == 0) out[0] = sh[0] / (float)NPTS;
}

// ---------------- host ----------------
static float* symaddr(const void* sym) {
    void* p = nullptr;
    cudaGetSymbolAddress(&p, sym);
    return (float*)p;
}

extern "C" void kernel_launch(void* const* d_in, const int* in_sizes, int n_in,
                              void* d_out, int out_size) {
    const float* x1 = (const float*)d_in[0];
    const float* x2 = (const float*)d_in[1];
    const float* w  = (const float*)d_in[2];

    float* an  = symaddr(d_an);
    float* bn  = symaddr(d_bn);
    float* Gxy = symaddr(d_Gxy);
    float* Gyx = symaddr(d_Gyx);
    float* Gxx = symaddr(d_Gxx);
    float* Gyy = symaddr(d_Gyy);
    float* fb  = symaddr(d_f);    // [2][NPTS]
    float* gb  = symaddr(d_g);
    float* xb  = symaddr(d_fxx);
    float* yb  = symaddr(d_gyy);
    float* ffin = symaddr(d_ffin);
    float* gfin = symaddr(d_gfin);
    float* xfin = symaddr(d_xfin);
    float* yfin = symaddr(d_yfin);

    wprep_kernel<<<1, DIM>>>(w);
    rownorm_kernel<<<2 * NPTS, DIM>>>(x1, x2);
    zero_kernel<<<NPTS / 256, 256>>>();

    dim3 ggrid(NPTS / 128, NPTS / 128);
    gemm_nt<<<ggrid, 256>>>(an, bn, Gxy, Gyx, 0);
    gemm_nt<<<ggrid, 256>>>(an, an, Gxx, Gxx, 1);
    gemm_nt<<<ggrid, 256>>>(bn, bn, Gyy, Gyy, 1);

    const float eps_list[10] = {4.0f, 1.0f, 0.25f, 0.0625f, 0.015625f,
                                0.00390625f, 0.0025f, 0.0025f, 0.0025f, 0.0025f};
    int cur = 0;
    for (int i = 0; i < 10; ++i) {
        float eps = eps_list[i];
        int nxt = 1 - cur;
        // symmetric (debiasing) potentials, averaged update
        softmin_kernel<<<NPTS, 256>>>(Gxx, xb + cur * NPTS, xb + cur * NPTS, xb + nxt * NPTS, eps, 1);
        softmin_kernel<<<NPTS, 256>>>(Gyy, yb + cur * NPTS, yb + cur * NPTS, yb + nxt * NPTS, eps, 1);
        // cross potentials, Jacobi (use old f and old g)
        softmin_kernel<<<NPTS, 256>>>(Gxy, gb + cur * NPTS, nullptr, fb + nxt * NPTS, eps, 0);
        softmin_kernel<<<NPTS, 256>>>(Gyx, fb + cur * NPTS, nullptr, gb + nxt * NPTS, eps, 0);
        cur = nxt;
    }

    const float epsF = 0.0025f;
    softmin_kernel<<<NPTS, 256>>>(Gxy, gb + cur * NPTS, nullptr, ffin, epsF, 0);
    softmin_kernel<<<NPTS, 256>>>(Gyx, fb + cur * NPTS, nullptr, gfin, epsF, 0);
    softmin_kernel<<<NPTS, 256>>>(Gxx, xb + cur * NPTS, nullptr, xfin, epsF, 0);
    softmin_kernel<<<NPTS, 256>>>(Gyy, yb + cur * NPTS, nullptr, yfin, epsF, 0);

    final_reduce<<<1, 1024>>>((float*)d_out);
}

// round 2
// speedup vs baseline: 1.9140x; 1.9140x over previous
#include <cuda_runtime.h>
#include <cuda_fp16.h>
#include <math.h>

#define NPTS 8192
#define DIM 256

// ---------------- static device scratch (no allocation allowed) ----------------
__device__ float  d_wc[DIM];
__device__ float  d_an[(size_t)NPTS * DIM];
__device__ float  d_bn[(size_t)NPTS * DIM];
__device__ __half d_Gxy[(size_t)NPTS * NPTS];   // an . bn^T
__device__ __half d_Gyx[(size_t)NPTS * NPTS];   // transpose of Gxy
__device__ __half d_Gxx[(size_t)NPTS * NPTS];   // an . an^T
__device__ __half d_Gyy[(size_t)NPTS * NPTS];   // bn . bn^T
__device__ float  d_f[2][NPTS];
__device__ float  d_g[2][NPTS];
__device__ float  d_fxx[2][NPTS];
__device__ float  d_gyy[2][NPTS];
__device__ float  d_ffin[NPTS], d_gfin[NPTS], d_xfin[NPTS], d_yfin[NPTS];

__device__ __forceinline__ float ex2f_fast(float x) {
    float y; asm("ex2.approx.ftz.f32 %0, %1;" : "=f"(y) : "f"(x)); return y;
}

// ---------------- prep: clip+renormalize w ----------------
__global__ void wprep_kernel(const float* __restrict__ w) {
    __shared__ float sh[DIM];
    int t = threadIdx.x;
    float c = fminf(fmaxf(w[t], 0.0f), 2.0f);
    sh[t] = c;
    __syncthreads();
    for (int off = DIM / 2; off > 0; off >>= 1) {
        if (t < off) sh[t] += sh[t + off];
        __syncthreads();
    }
    float S = sh[0];
    d_wc[t] = c * ((float)DIM / S);
}

// ---------------- prep: row-normalize an (with wc) and bn ----------------
__global__ void rownorm_kernel(const float* __restrict__ x1, const float* __restrict__ x2) {
    __shared__ float sh[DIM];
    int b = blockIdx.x, t = threadIdx.x;
    float v;
    if (b < NPTS) v = d_wc[t] * x1[(size_t)b * DIM + t];
    else          v = x2[(size_t)(b - NPTS) * DIM + t];
    sh[t] = v * v;
    __syncthreads();
    for (int off = DIM / 2; off > 0; off >>= 1) {
        if (t < off) sh[t] += sh[t + off];
        __syncthreads();
    }
    float inv = 1.0f / (sqrtf(sh[0]) + 1e-12f);
    if (b < NPTS) d_an[(size_t)b * DIM + t] = v * inv;
    else          d_bn[(size_t)(b - NPTS) * DIM + t] = v * inv;
}

// ---------------- zero potentials ----------------
__global__ void zero_kernel() {
    int i = blockIdx.x * blockDim.x + threadIdx.x;
    if (i < NPTS) {
        d_f[0][i] = 0.0f; d_g[0][i] = 0.0f;
        d_fxx[0][i] = 0.0f; d_gyy[0][i] = 0.0f;
    }
}

// ---------------- GEMM: C = A * B^T, fp16 output ----------------
__global__ void __launch_bounds__(256) gemm_nt(const float* __restrict__ A,
                                               const float* __restrict__ B,
                                               __half* __restrict__ C,
                                               __half* __restrict__ CT,
                                               int sym) {
    int btx = blockIdx.x, bty = blockIdx.y;
    if (sym && btx > bty) return;

    __shared__ float As[16][128];
    __shared__ float Bs[16][128];

    int tid = threadIdx.x;
    int tx = tid & 15, ty = tid >> 4;
    int rowBase = bty * 128, colBase = btx * 128;

    float acc[8][8];
#pragma unroll
    for (int r = 0; r < 8; ++r)
#pragma unroll
        for (int c = 0; c < 8; ++c) acc[r][c] = 0.0f;

    for (int kt = 0; kt < DIM; kt += 16) {
#pragma unroll
        for (int q = 0; q < 2; ++q) {
            int li = q * 256 + tid;
            int r  = li >> 2;
            int k4 = (li & 3) * 4;
            float4 va = *(const float4*)(A + (size_t)(rowBase + r) * DIM + kt + k4);
            As[k4 + 0][r] = va.x; As[k4 + 1][r] = va.y;
            As[k4 + 2][r] = va.z; As[k4 + 3][r] = va.w;
            float4 vb = *(const float4*)(B + (size_t)(colBase + r) * DIM + kt + k4);
            Bs[k4 + 0][r] = vb.x; Bs[k4 + 1][r] = vb.y;
            Bs[k4 + 2][r] = vb.z; Bs[k4 + 3][r] = vb.w;
        }
        __syncthreads();
#pragma unroll
        for (int kk = 0; kk < 16; ++kk) {
            float a[8], b[8];
            *(float4*)(a)     = *(const float4*)&As[kk][ty * 8];
            *(float4*)(a + 4) = *(const float4*)&As[kk][ty * 8 + 4];
            *(float4*)(b)     = *(const float4*)&Bs[kk][tx * 8];
            *(float4*)(b + 4) = *(const float4*)&Bs[kk][tx * 8 + 4];
#pragma unroll
            for (int r = 0; r < 8; ++r)
#pragma unroll
                for (int c = 0; c < 8; ++c)
                    acc[r][c] = fmaf(a[r], b[c], acc[r][c]);
        }
        __syncthreads();
    }

    // normal epilogue: 8 halves per row = one uint4 store
#pragma unroll
    for (int r = 0; r < 8; ++r) {
        __half2 q0 = __floats2half2_rn(acc[r][0], acc[r][1]);
        __half2 q1 = __floats2half2_rn(acc[r][2], acc[r][3]);
        __half2 q2 = __floats2half2_rn(acc[r][4], acc[r][5]);
        __half2 q3 = __floats2half2_rn(acc[r][6], acc[r][7]);
        uint4 pk;
        pk.x = *(unsigned*)&q0; pk.y = *(unsigned*)&q1;
        pk.z = *(unsigned*)&q2; pk.w = *(unsigned*)&q3;
        size_t base = (size_t)(rowBase + ty * 8 + r) * NPTS + colBase + tx * 8;
        *(uint4*)(C + base) = pk;
    }
    // transposed epilogue
    if (CT != nullptr && !(sym && btx == bty)) {
#pragma unroll
        for (int c = 0; c < 8; ++c) {
            __half2 q0 = __floats2half2_rn(acc[0][c], acc[1][c]);
            __half2 q1 = __floats2half2_rn(acc[2][c], acc[3][c]);
            __half2 q2 = __floats2half2_rn(acc[4][c], acc[5][c]);
            __half2 q3 = __floats2half2_rn(acc[6][c], acc[7][c]);
            uint4 pk;
            pk.x = *(unsigned*)&q0; pk.y = *(unsigned*)&q1;
            pk.z = *(unsigned*)&q2; pk.w = *(unsigned*)&q3;
            size_t base = (size_t)(colBase + tx * 8 + c) * NPTS + rowBase + ty * 8;
            *(uint4*)(CT + base) = pk;
        }
    }
}

// ---------------- fused softmin over up to 4 (G, pot) variants ----------------
// out_i = -eps*(log_w + LSE_j((pot_j - 1 + G_ij)/eps)); avg: 0.5*(old + r)
struct SMArgs {
    const __half* G[4];
    const float*  pot[4];
    const float*  oldpot[4];
    float*        out[4];
    int           avg[4];
};

__global__ void __launch_bounds__(256) softmin4(SMArgs args, float eps) {
    const int var = blockIdx.y;
    const int row = blockIdx.x;
    const int tid = threadIdx.x;
    const int lane = tid & 31, wid = tid >> 5;

    const __half* Grow = args.G[var] + (size_t)row * NPTS;
    const float*  pot  = args.pot[var];

    const float L2E = 1.4426950408889634f;
    const float c1 = L2E / eps;     // u = (pot + G - 1) * L2E/eps
    const float c0 = -c1;

    float u[32];
    float tm = -INFINITY;
#pragma unroll
    for (int it = 0; it < 8; ++it) {
        int idx = it * 256 + tid;                       // 4-element group index
        uint2 graw = ((const uint2*)Grow)[idx];         // 4 halves
        float4 p   = ((const float4*)pot)[idx];         // 4 pot values (L1-hot)
        float2 g01 = __half22float2(*(const __half2*)&graw.x);
        float2 g23 = __half22float2(*(const __half2*)&graw.y);
        float u0 = fmaf(g01.x + p.x, c1, c0);
        float u1 = fmaf(g01.y + p.y, c1, c0);
        float u2 = fmaf(g23.x + p.z, c1, c0);
        float u3 = fmaf(g23.y + p.w, c1, c0);
        u[it * 4 + 0] = u0; u[it * 4 + 1] = u1;
        u[it * 4 + 2] = u2; u[it * 4 + 3] = u3;
        tm = fmaxf(tm, fmaxf(fmaxf(u0, u1), fmaxf(u2, u3)));
    }

    // block max
#pragma unroll
    for (int off = 16; off > 0; off >>= 1)
        tm = fmaxf(tm, __shfl_xor_sync(0xffffffffu, tm, off));
    __shared__ float sred[8];
    __shared__ float ssum[8];
    if (lane == 0) sred[wid] = tm;
    __syncthreads();
    float M = sred[0];
#pragma unroll
    for (int i = 1; i < 8; ++i) M = fmaxf(M, sred[i]);

    // exp phase with warp-level sparsity skip (tm is warp-uniform here)
    float s = 0.0f;
    if (tm >= M - 40.0f) {
        float s0 = 0.f, s1 = 0.f, s2 = 0.f, s3 = 0.f;
#pragma unroll
        for (int i = 0; i < 32; i += 4) {
            s0 += ex2f_fast(u[i + 0] - M);
            s1 += ex2f_fast(u[i + 1] - M);
            s2 += ex2f_fast(u[i + 2] - M);
            s3 += ex2f_fast(u[i + 3] - M);
        }
        s = (s0 + s1) + (s2 + s3);
    }
#pragma unroll
    for (int off = 16; off > 0; off >>= 1)
        s += __shfl_xor_sync(0xffffffffu, s, off);
    if (lane == 0) ssum[wid] = s;
    __syncthreads();
    if (tid == 0) {
        float S = ((ssum[0] + ssum[1]) + (ssum[2] + ssum[3]))
                + ((ssum[4] + ssum[5]) + (ssum[6] + ssum[7]));
        const float LOGW = -9.010913347279288f;   // -log(8192)
        const float LN2  = 0.6931471805599453f;
        float lse = (M + log2f(S)) * LN2;
        float r = -eps * (LOGW + lse);
        if (args.avg[var]) r = 0.5f * (args.oldpot[var][row] + r);
        args.out[var][row] = r;
    }
}

// ---------------- final reduction ----------------
__global__ void final_reduce(float* __restrict__ out) {
    __shared__ float sh[1024];
    int t = threadIdx.x;
    float s = 0.0f;
    for (int i = t; i < NPTS; i += 1024)
        s += (d_ffin[i] - d_xfin[i]) + (d_gfin[i] - d_yfin[i]);
    sh[t] = s;
    __syncthreads();
    for (int off = 512; off > 0; off >>= 1) {
        if (t < off) sh[t] += sh[t + off];
        __syncthreads();
    }
    if (t == 0) out[0] = sh[0] / (float)NPTS;
}

// ---------------- host ----------------
static void* symaddr(const void* sym) {
    void* p = nullptr;
    cudaGetSymbolAddress(&p, sym);
    return p;
}

extern "C" void kernel_launch(void* const* d_in, const int* in_sizes, int n_in,
                              void* d_out, int out_size) {
    const float* x1 = (const float*)d_in[0];
    const float* x2 = (const float*)d_in[1];
    const float* w  = (const float*)d_in[2];

    float*  an  = (float*)symaddr(d_an);
    float*  bn  = (float*)symaddr(d_bn);
    __half* Gxy = (__half*)symaddr(d_Gxy);
    __half* Gyx = (__half*)symaddr(d_Gyx);
    __half* Gxx = (__half*)symaddr(d_Gxx);
    __half* Gyy = (__half*)symaddr(d_Gyy);
    float* fb  = (float*)symaddr(d_f);
    float* gb  = (float*)symaddr(d_g);
    float* xb  = (float*)symaddr(d_fxx);
    float* yb  = (float*)symaddr(d_gyy);
    float* ffin = (float*)symaddr(d_ffin);
    float* gfin = (float*)symaddr(d_gfin);
    float* xfin = (float*)symaddr(d_xfin);
    float* yfin = (float*)symaddr(d_yfin);

    wprep_kernel<<<1, DIM>>>(w);
    rownorm_kernel<<<2 * NPTS, DIM>>>(x1, x2);
    zero_kernel<<<NPTS / 256, 256>>>();

    dim3 ggrid(NPTS / 128, NPTS / 128);
    gemm_nt<<<ggrid, 256>>>(an, bn, Gxy, Gyx, 0);
    gemm_nt<<<ggrid, 256>>>(an, an, Gxx, Gxx, 1);
    gemm_nt<<<ggrid, 256>>>(bn, bn, Gyy, Gyy, 1);

    const float eps_list[10] = {4.0f, 1.0f, 0.25f, 0.0625f, 0.015625f,
                                0.00390625f, 0.0025f, 0.0025f, 0.0025f, 0.0025f};
    int cur = 0;
    for (int i = 0; i < 10; ++i) {
        float eps = eps_list[i];
        int nxt = 1 - cur;
        SMArgs a;
        // var 0: fxx (Gxx, averaged) | var 1: gyy (Gyy, averaged)
        // var 2: f <- softmin(Gxy, g) | var 3: g <- softmin(Gyx, f)
        a.G[0] = Gxx;  a.pot[0] = xb + cur * NPTS; a.oldpot[0] = xb + cur * NPTS; a.out[0] = xb + nxt * NPTS; a.avg[0] = 1;
        a.G[1] = Gyy;  a.pot[1] = yb + cur * NPTS; a.oldpot[1] = yb + cur * NPTS; a.out[1] = yb + nxt * NPTS; a.avg[1] = 1;
        a.G[2] = Gxy;  a.pot[2] = gb + cur * NPTS; a.oldpot[2] = nullptr;         a.out[2] = fb + nxt * NPTS; a.avg[2] = 0;
        a.G[3] = Gyx;  a.pot[3] = fb + cur * NPTS; a.oldpot[3] = nullptr;         a.out[3] = gb + nxt * NPTS; a.avg[3] = 0;
        softmin4<<<dim3(NPTS, 4), 256>>>(a, eps);
        cur = nxt;
    }

    const float epsF = 0.0025f;
    {
        SMArgs a;
        a.G[0] = Gxy; a.pot[0] = gb + cur * NPTS; a.oldpot[0] = nullptr; a.out[0] = ffin; a.avg[0] = 0;
        a.G[1] = Gyx; a.pot[1] = fb + cur * NPTS; a.oldpot[1] = nullptr; a.out[1] = gfin; a.avg[1] = 0;
        a.G[2] = Gxx; a.pot[2] = xb + cur * NPTS; a.oldpot[2] = nullptr; a.out[2] = xfin; a.avg[2] = 0;
        a.G[3] = Gyy; a.pot[3] = yb + cur * NPTS; a.oldpot[3] = nullptr; a.out[3] = yfin; a.avg[3] = 0;
        softmin4<<<dim3(NPTS, 4), 256>>>(a, epsF);
    }

    final_reduce<<<1, 1024>>>((float*)d_out);
}

// round 4
// speedup vs baseline: 2.8135x; 1.4700x over previous
#include <cuda_runtime.h>
#include <cuda_fp16.h>
#include <math.h>
#include <stdint.h>

#define NPTS 8192
#define DIM 256

// ---------------- static device scratch (no allocation allowed) ----------------
__device__ float  d_wc[DIM];
__device__ __half d_anh[(size_t)NPTS * DIM];
__device__ __half d_bnh[(size_t)NPTS * DIM];
__device__ __half d_Gxy[(size_t)NPTS * NPTS];
__device__ __half d_Gyx[(size_t)NPTS * NPTS];
__device__ __half d_Gxx[(size_t)NPTS * NPTS];
__device__ __half d_Gyy[(size_t)NPTS * NPTS];
__device__ float  d_f[2][NPTS];
__device__ float  d_g[2][NPTS];
__device__ float  d_fxx[2][NPTS];
__device__ float  d_gyy[2][NPTS];
__device__ float  d_ffin[NPTS], d_gfin[NPTS], d_xfin[NPTS], d_yfin[NPTS];

__device__ __forceinline__ float ex2f_fast(float x) {
    float y; asm("ex2.approx.ftz.f32 %0, %1;" : "=f"(y) : "f"(x)); return y;
}
__device__ __forceinline__ uint32_t smem_u32(const void* p) {
    uint32_t a;
    asm("{ .reg .u64 t; cvta.to.shared.u64 t, %1; cvt.u32.u64 %0, t; }" : "=r"(a) : "l"(p));
    return a;
}

// ---------------- prep: clip+renormalize w ----------------
__global__ void wprep_kernel(const float* __restrict__ w) {
    __shared__ float sh[DIM];
    int t = threadIdx.x;
    float c = fminf(fmaxf(w[t], 0.0f), 2.0f);
    sh[t] = c;
    __syncthreads();
    for (int off = DIM / 2; off > 0; off >>= 1) {
        if (t < off) sh[t] += sh[t + off];
        __syncthreads();
    }
    float S = sh[0];
    d_wc[t] = c * ((float)DIM / S);
}

// ---------------- prep: row-normalize -> fp16 ----------------
__global__ void rownorm_kernel(const float* __restrict__ x1, const float* __restrict__ x2) {
    __shared__ float sh[DIM];
    int b = blockIdx.x, t = threadIdx.x;
    float v;
    if (b < NPTS) v = d_wc[t] * x1[(size_t)b * DIM + t];
    else          v = x2[(size_t)(b - NPTS) * DIM + t];
    sh[t] = v * v;
    __syncthreads();
    for (int off = DIM / 2; off > 0; off >>= 1) {
        if (t < off) sh[t] += sh[t + off];
        __syncthreads();
    }
    float inv = 1.0f / (sqrtf(sh[0]) + 1e-12f);
    __half h = __float2half_rn(v * inv);
    if (b < NPTS) d_anh[(size_t)b * DIM + t] = h;
    else          d_bnh[(size_t)(b - NPTS) * DIM + t] = h;
}

__global__ void zero_kernel() {
    int i = blockIdx.x * blockDim.x + threadIdx.x;
    if (i < NPTS) {
        d_f[0][i] = 0.0f; d_g[0][i] = 0.0f;
        d_fxx[0][i] = 0.0f; d_gyy[0][i] = 0.0f;
    }
}

// ---------------- HMMA GEMM: C = A * B^T, fp16 in/out, fp32 accum ----------------
// CTA tile 128(m) x 64(n), K=256 in two 128-chunks. 8 warps in 2(m) x 4(n) grid;
// warp tile 64 x 16 -> MI=4 m16 tiles, NI=2 n8 tiles.
// SMEM: XOR-swizzled (SW128-style) 64-half sections, conflict-free ldmatrix.

#define BM 128
#define BN 64
// As: 128 rows x 128 halves per chunk = 32KB (two 16KB sections of 64 halves)
// Bs:  64 rows x 128 halves per chunk = 16KB (two  8KB sections)
__global__ void __launch_bounds__(256) gemm_mma(const __half* __restrict__ A,
                                                const __half* __restrict__ B,
                                                __half* __restrict__ C) {
    __shared__ char smem[49152];
    char* As = smem;
    char* Bs = smem + 32768;
    const uint32_t As_u = smem_u32(As);
    const uint32_t Bs_u = smem_u32(Bs);

    const int tid = threadIdx.x;
    const int wid = tid >> 5, lane = tid & 31;
    const int warp_m = wid >> 2, warp_n = wid & 3;
    const int rowBase = blockIdx.y * BM;
    const int colBase = blockIdx.x * BN;

    float acc[4][2][4];
#pragma unroll
    for (int mi = 0; mi < 4; ++mi)
#pragma unroll
        for (int ni = 0; ni < 2; ++ni)
#pragma unroll
            for (int q = 0; q < 4; ++q) acc[mi][ni][q] = 0.0f;

    // precompute per-lane ldmatrix row components
    const int mat = lane >> 3, rin = lane & 7;
    // A frag: matrices (m0-7,k0-7),(m8-15,k0-7),(m0-7,k8-15),(m8-15,k8-15)
    const int a_row_in = (mat & 1) * 8 + rin;        // + mi*16 + warp_m*64
    const int a_khalf  = (mat >> 1) * 8;             // + ks*16
    // B frag (x4 covers ni pair): matrices (n0-7,k0-7),(n0-7,k8-15),(n8-15,k0-7),(n8-15,k8-15)
    const int b_row_in = (mat >> 1) * 8 + rin;       // + warp_n*16
    const int b_khalf  = (mat & 1) * 8;              // + ks*16

    for (int kc = 0; kc < 2; ++kc) {
        // ---- load chunk into swizzled smem ----
#pragma unroll
        for (int i = tid; i < 2048; i += 256) {       // A: 128 rows x 16 chunks
            int r = i >> 4, ch = i & 15;
            int s = ch >> 3, cw16 = ch & 7;
            int addr = s * 16384 + r * 128 + (((cw16) ^ (r & 7)) << 4);
            *(uint4*)(As + addr) =
                *(const uint4*)(A + (size_t)(rowBase + r) * DIM + kc * 128 + ch * 8);
        }
#pragma unroll
        for (int i = tid; i < 1024; i += 256) {       // B: 64 rows x 16 chunks
            int r = i >> 4, ch = i & 15;
            int s = ch >> 3, cw16 = ch & 7;
            int addr = s * 8192 + r * 128 + (((cw16) ^ (r & 7)) << 4);
            *(uint4*)(Bs + addr) =
                *(const uint4*)(B + (size_t)(colBase + r) * DIM + kc * 128 + ch * 8);
        }
        __syncthreads();

        // ---- 8 k-steps of mma ----
#pragma unroll
        for (int ks = 0; ks < 8; ++ks) {
            // B fragments for the warp's two n8 tiles (single ldmatrix.x4)
            uint32_t bf[4];
            {
                int nrow = warp_n * 16 + b_row_in;
                int kcol = ks * 16 + b_khalf;
                int s = kcol >> 6, cw16 = (kcol & 63) >> 3;
                uint32_t addr = Bs_u + s * 8192 + nrow * 128 + ((cw16 ^ (nrow & 7)) << 4);
                asm volatile("ldmatrix.sync.aligned.m8n8.x4.shared.b16 {%0,%1,%2,%3}, [%4];"
                             : "=r"(bf[0]), "=r"(bf[1]), "=r"(bf[2]), "=r"(bf[3])
                             : "r"(addr));
            }
#pragma unroll
            for (int mi = 0; mi < 4; ++mi) {
                uint32_t af[4];
                int arow = warp_m * 64 + mi * 16 + a_row_in;
                int kcol = ks * 16 + a_khalf;
                int s = kcol >> 6, cw16 = (kcol & 63) >> 3;
                uint32_t addr = As_u + s * 16384 + arow * 128 + ((cw16 ^ (arow & 7)) << 4);
                asm volatile("ldmatrix.sync.aligned.m8n8.x4.shared.b16 {%0,%1,%2,%3}, [%4];"
                             : "=r"(af[0]), "=r"(af[1]), "=r"(af[2]), "=r"(af[3])
                             : "r"(addr));
#pragma unroll
                for (int ni = 0; ni < 2; ++ni) {
                    asm volatile(
                        "mma.sync.aligned.m16n8k16.row.col.f32.f16.f16.f32 "
                        "{%0,%1,%2,%3}, {%4,%5,%6,%7}, {%8,%9}, {%0,%1,%2,%3};"
                        : "+f"(acc[mi][ni][0]), "+f"(acc[mi][ni][1]),
                          "+f"(acc[mi][ni][2]), "+f"(acc[mi][ni][3])
                        : "r"(af[0]), "r"(af[1]), "r"(af[2]), "r"(af[3]),
                          "r"(bf[ni * 2]), "r"(bf[ni * 2 + 1]));
                }
            }
        }
        __syncthreads();
    }

    // ---- epilogue: stage fp16 tile in padded smem (stride 72 halves), then coalesce ----
    // Stage size: 128 * 144B = 18432 bytes (reuses As).
    __half* stage = (__half*)smem;
#pragma unroll
    for (int mi = 0; mi < 4; ++mi)
#pragma unroll
        for (int ni = 0; ni < 2; ++ni) {
            int row = warp_m * 64 + mi * 16 + (lane >> 2);
            int col = warp_n * 16 + ni * 8 + 2 * (lane & 3);
            __half2 lo = __floats2half2_rn(acc[mi][ni][0], acc[mi][ni][1]);
            __half2 hi = __floats2half2_rn(acc[mi][ni][2], acc[mi][ni][3]);
            *(__half2*)(stage + row * 72 + col)       = lo;
            *(__half2*)(stage + (row + 8) * 72 + col) = hi;
        }
    __syncthreads();
#pragma unroll
    for (int i = tid; i < 1024; i += 256) {   // 128 rows x 8 uint4-chunks
        int r = i >> 3, ch = i & 7;
        uint4 v = *(uint4*)(stage + r * 72 + ch * 8);
        *(uint4*)(C + (size_t)(rowBase + r) * NPTS + colBase + ch * 8) = v;
    }
}

// ---------------- fused softmin over 4 (G, pot) variants ----------------
struct SMArgs {
    const __half* G[4];
    const float*  pot[4];
    const float*  oldpot[4];
    float*        out[4];
    int           avg[4];
};

__global__ void __launch_bounds__(256) softmin4(SMArgs args, float eps) {
    const int var = blockIdx.y;
    const int row = blockIdx.x;
    const int tid = threadIdx.x;
    const int lane = tid & 31, wid = tid >> 5;

    const __half* Grow = args.G[var] + (size_t)row * NPTS;
    const float*  pot  = args.pot[var];

    const float L2E = 1.4426950408889634f;
    const float c1 = L2E / eps;
    const float c0 = -c1;

    float u[32];
    float tm = -INFINITY;
#pragma unroll
    for (int it = 0; it < 8; ++it) {
        int idx = it * 256 + tid;
        uint2 graw = ((const uint2*)Grow)[idx];
        float4 p   = ((const float4*)pot)[idx];
        float2 g01 = __half22float2(*(const __half2*)&graw.x);
        float2 g23 = __half22float2(*(const __half2*)&graw.y);
        float u0 = fmaf(g01.x + p.x, c1, c0);
        float u1 = fmaf(g01.y + p.y, c1, c0);
        float u2 = fmaf(g23.x + p.z, c1, c0);
        float u3 = fmaf(g23.y + p.w, c1, c0);
        u[it * 4 + 0] = u0; u[it * 4 + 1] = u1;
        u[it * 4 + 2] = u2; u[it * 4 + 3] = u3;
        tm = fmaxf(tm, fmaxf(fmaxf(u0, u1), fmaxf(u2, u3)));
    }

#pragma unroll
    for (int off = 16; off > 0; off >>= 1)
        tm = fmaxf(tm, __shfl_xor_sync(0xffffffffu, tm, off));
    __shared__ float sred[8];
    __shared__ float ssum[8];
    if (lane == 0) sred[wid] = tm;
    __syncthreads();
    float M = sred[0];
#pragma unroll
    for (int i = 1; i < 8; ++i) M = fmaxf(M, sred[i]);

    float s = 0.0f;
    if (tm >= M - 40.0f) {
        float s0 = 0.f, s1 = 0.f, s2 = 0.f, s3 = 0.f;
#pragma unroll
        for (int i = 0; i < 32; i += 4) {
            s0 += ex2f_fast(u[i + 0] - M);
            s1 += ex2f_fast(u[i + 1] - M);
            s2 += ex2f_fast(u[i + 2] - M);
            s3 += ex2f_fast(u[i + 3] - M);
        }
        s = (s0 + s1) + (s2 + s3);
    }
#pragma unroll
    for (int off = 16; off > 0; off >>= 1)
        s += __shfl_xor_sync(0xffffffffu, s, off);
    if (lane == 0) ssum[wid] = s;
    __syncthreads();
    if (tid == 0) {
        float S = ((ssum[0] + ssum[1]) + (ssum[2] + ssum[3]))
                + ((ssum[4] + ssum[5]) + (ssum[6] + ssum[7]));
        const float LOGW = -9.010913347279288f;
        const float LN2  = 0.6931471805599453f;
        float lse = (M + log2f(S)) * LN2;
        float r = -eps * (LOGW + lse);
        if (args.avg[var]) r = 0.5f * (args.oldpot[var][row] + r);
        args.out[var][row] = r;
    }
}

// ---------------- final reduction ----------------
__global__ void final_reduce(float* __restrict__ out) {
    __shared__ float sh[1024];
    int t = threadIdx.x;
    float s = 0.0f;
    for (int i = t; i < NPTS; i += 1024)
        s += (d_ffin[i] - d_xfin[i]) + (d_gfin[i] - d_yfin[i]);
    sh[t] = s;
    __syncthreads();
    for (int off = 512; off > 0; off >>= 1) {
        if (t < off) sh[t] += sh[t + off];
        __syncthreads();
    }
    if (t == 0) out[0] = sh[0] / (float)NPTS;
}

// ---------------- host ----------------
static void* symaddr(const void* sym) {
    void* p = nullptr;
    cudaGetSymbolAddress(&p, sym);
    return p;
}

extern "C" void kernel_launch(void* const* d_in, const int* in_sizes, int n_in,
                              void* d_out, int out_size) {
    const float* x1 = (const float*)d_in[0];
    const float* x2 = (const float*)d_in[1];
    const float* w  = (const float*)d_in[2];

    __half* an  = (__half*)symaddr(d_anh);
    __half* bn  = (__half*)symaddr(d_bnh);
    __half* Gxy = (__half*)symaddr(d_Gxy);
    __half* Gyx = (__half*)symaddr(d_Gyx);
    __half* Gxx = (__half*)symaddr(d_Gxx);
    __half* Gyy = (__half*)symaddr(d_Gyy);
    float* fb  = (float*)symaddr(d_f);
    float* gb  = (float*)symaddr(d_g);
    float* xb  = (float*)symaddr(d_fxx);
    float* yb  = (float*)symaddr(d_gyy);
    float* ffin = (float*)symaddr(d_ffin);
    float* gfin = (float*)symaddr(d_gfin);
    float* xfin = (float*)symaddr(d_xfin);
    float* yfin = (float*)symaddr(d_yfin);

    wprep_kernel<<<1, DIM>>>(w);
    rownorm_kernel<<<2 * NPTS, DIM>>>(x1, x2);
    zero_kernel<<<NPTS / 256, 256>>>();

    dim3 ggrid(NPTS / BN, NPTS / BM);
    gemm_mma<<<ggrid, 256>>>(an, bn, Gxy);
    gemm_mma<<<ggrid, 256>>>(bn, an, Gyx);
    gemm_mma<<<ggrid, 256>>>(an, an, Gxx);
    gemm_mma<<<ggrid, 256>>>(bn, bn, Gyy);

    const float eps_list[10] = {4.0f, 1.0f, 0.25f, 0.0625f, 0.015625f,
                                0.00390625f, 0.0025f, 0.0025f, 0.0025f, 0.0025f};
    int cur = 0;
    for (int i = 0; i < 10; ++i) {
        float eps = eps_list[i];
        int nxt = 1 - cur;
        SMArgs a;
        a.G[0] = Gxx;  a.pot[0] = xb + cur * NPTS; a.oldpot[0] = xb + cur * NPTS; a.out[0] = xb + nxt * NPTS; a.avg[0] = 1;
        a.G[1] = Gyy;  a.pot[1] = yb + cur * NPTS; a.oldpot[1] = yb + cur * NPTS; a.out[1] = yb + nxt * NPTS; a.avg[1] = 1;
        a.G[2] = Gxy;  a.pot[2] = gb + cur * NPTS; a.oldpot[2] = nullptr;         a.out[2] = fb + nxt * NPTS; a.avg[2] = 0;
        a.G[3] = Gyx;  a.pot[3] = fb + cur * NPTS; a.oldpot[3] = nullptr;         a.out[3] = gb + nxt * NPTS; a.avg[3] = 0;
        softmin4<<<dim3(NPTS, 4), 256>>>(a, eps);
        cur = nxt;
    }

    const float epsF = 0.0025f;
    {
        SMArgs a;
        a.G[0] = Gxy; a.pot[0] = gb + cur * NPTS; a.oldpot[0] = nullptr; a.out[0] = ffin; a.avg[0] = 0;
        a.G[1] = Gyx; a.pot[1] = fb + cur * NPTS; a.oldpot[1] = nullptr; a.out[1] = gfin; a.avg[1] = 0;
        a.G[2] = Gxx; a.pot[2] = xb + cur * NPTS; a.oldpot[2] = nullptr; a.out[2] = xfin; a.avg[2] = 0;
        a.G[3] = Gyy; a.pot[3] = yb + cur * NPTS; a.oldpot[3] = nullptr; a.out[3] = yfin; a.avg[3] = 0;
        softmin4<<<dim3(NPTS, 4), 256>>>(a, epsF);
    }

    final_reduce<<<1, 1024>>>((float*)d_out);
}

// round 5
// speedup vs baseline: 3.6396x; 1.2936x over previous
#include <cuda_runtime.h>
#include <cuda_fp16.h>
#include <math.h>
#include <stdint.h>

#define NPTS 8192
#define DIM 256
#define KC 64
#define NCHUNK (DIM / KC)

// ---------------- static device scratch (no allocation allowed) ----------------
__device__ float  d_wc[DIM];
__device__ __half d_anh[(size_t)NPTS * DIM];
__device__ __half d_bnh[(size_t)NPTS * DIM];
__device__ __half d_Gxy[(size_t)NPTS * NPTS];
__device__ __half d_Gyx[(size_t)NPTS * NPTS];
__device__ __half d_Gxx[(size_t)NPTS * NPTS];
__device__ __half d_Gyy[(size_t)NPTS * NPTS];
__device__ float  d_f[2][NPTS];
__device__ float  d_g[2][NPTS];
__device__ float  d_fxx[2][NPTS];
__device__ float  d_gyy[2][NPTS];
__device__ float  d_ffin[NPTS], d_gfin[NPTS], d_xfin[NPTS], d_yfin[NPTS];

__device__ __forceinline__ float ex2f_fast(float x) {
    float y; asm("ex2.approx.ftz.f32 %0, %1;" : "=f"(y) : "f"(x)); return y;
}
__device__ __forceinline__ uint32_t smem_u32(const void* p) {
    uint32_t a;
    asm("{ .reg .u64 t; cvta.to.shared.u64 t, %1; cvt.u32.u64 %0, t; }" : "=r"(a) : "l"(p));
    return a;
}
__device__ __forceinline__ void cp_async16(uint32_t dst, const void* src) {
    asm volatile("cp.async.cg.shared.global [%0], [%1], 16;" :: "r"(dst), "l"(src) : "memory");
}
#define LDMX4(r, addr)                                                          \
    asm volatile("ldmatrix.sync.aligned.m8n8.x4.shared.b16 {%0,%1,%2,%3}, [%4];" \
                 : "=r"((r)[0]), "=r"((r)[1]), "=r"((r)[2]), "=r"((r)[3])        \
                 : "r"(addr))

// ---------------- prep: clip+renormalize w ----------------
__global__ void wprep_kernel(const float* __restrict__ w) {
    __shared__ float sh[DIM];
    int t = threadIdx.x;
    float c = fminf(fmaxf(w[t], 0.0f), 2.0f);
    sh[t] = c;
    __syncthreads();
    for (int off = DIM / 2; off > 0; off >>= 1) {
        if (t < off) sh[t] += sh[t + off];
        __syncthreads();
    }
    float S = sh[0];
    d_wc[t] = c * ((float)DIM / S);
}

// ---------------- prep: row-normalize -> fp16 ----------------
__global__ void rownorm_kernel(const float* __restrict__ x1, const float* __restrict__ x2) {
    __shared__ float sh[DIM];
    int b = blockIdx.x, t = threadIdx.x;
    float v;
    if (b < NPTS) v = d_wc[t] * x1[(size_t)b * DIM + t];
    else          v = x2[(size_t)(b - NPTS) * DIM + t];
    sh[t] = v * v;
    __syncthreads();
    for (int off = DIM / 2; off > 0; off >>= 1) {
        if (t < off) sh[t] += sh[t + off];
        __syncthreads();
    }
    float inv = 1.0f / (sqrtf(sh[0]) + 1e-12f);
    __half h = __float2half_rn(v * inv);
    if (b < NPTS) d_anh[(size_t)b * DIM + t] = h;
    else          d_bnh[(size_t)(b - NPTS) * DIM + t] = h;
}

__global__ void zero_kernel() {
    int i = blockIdx.x * blockDim.x + threadIdx.x;
    if (i < NPTS) {
        d_f[0][i] = 0.0f; d_g[0][i] = 0.0f;
        d_fxx[0][i] = 0.0f; d_gyy[0][i] = 0.0f;
    }
}

// ---------------- HMMA GEMM: C = A * B^T (+ transposed output CT) ----------------
// CTA tile 128x128, 8 warps 2(m) x 4(n), warp tile 64x32.
// K=256 in 4 chunks of 64, cp.async double-buffered.
// smem: 2 buffers x (A 16KB + B 16KB) = 64KB dynamic.
__global__ void __launch_bounds__(256, 2) gemm_mma(const __half* __restrict__ A,
                                                   const __half* __restrict__ B,
                                                   __half* __restrict__ C,
                                                   __half* __restrict__ CT,
                                                   int sym) {
    extern __shared__ char smem[];
    const int btx = blockIdx.x, bty = blockIdx.y;
    if (sym && btx > bty) return;

    const uint32_t smem_base = smem_u32(smem);
    const int tid = threadIdx.x;
    const int wid = tid >> 5, lane = tid & 31;
    const int warp_m = wid >> 2, warp_n = wid & 3;
    const int rowBase = bty * 128;
    const int colBase = btx * 128;

    const int mat = lane >> 3, rin = lane & 7;
    const int a_row_in = (mat & 1) * 8 + rin;
    const int a_kh     = (mat >> 1) * 8;
    const int b_row_in = (mat >> 1) * 8 + rin;
    const int b_kh     = (mat & 1) * 8;

    float acc[4][4][4];
#pragma unroll
    for (int mi = 0; mi < 4; ++mi)
#pragma unroll
        for (int ni = 0; ni < 4; ++ni)
#pragma unroll
            for (int q = 0; q < 4; ++q) acc[mi][ni][q] = 0.0f;

    // ---- chunk-load issuer: A+B chunk c -> buffer b (one commit group) ----
#define ISSUE_CHUNK(c, b) do {                                                  \
        const __half* Asrc_ = A + (size_t)rowBase * DIM + (c) * KC;             \
        const __half* Bsrc_ = B + (size_t)colBase * DIM + (c) * KC;             \
        uint32_t Ab_ = smem_base + (b) * 32768;                                 \
        uint32_t Bb_ = Ab_ + 16384;                                             \
        _Pragma("unroll")                                                       \
        for (int q_ = 0; q_ < 4; ++q_) {                                        \
            int i_ = q_ * 256 + tid;                                            \
            int r_ = i_ >> 3, cw_ = i_ & 7;                                     \
            uint32_t off_ = r_ * 128 + (((uint32_t)(cw_ ^ (r_ & 7))) << 4);     \
            cp_async16(Ab_ + off_, Asrc_ + (size_t)r_ * DIM + cw_ * 8);         \
            cp_async16(Bb_ + off_, Bsrc_ + (size_t)r_ * DIM + cw_ * 8);         \
        }                                                                       \
        asm volatile("cp.async.commit_group;" ::: "memory");                    \
    } while (0)

    ISSUE_CHUNK(0, 0);
#pragma unroll
    for (int c = 0; c < NCHUNK; ++c) {
        if (c + 1 < NCHUNK) {
            ISSUE_CHUNK(c + 1, (c + 1) & 1);
            asm volatile("cp.async.wait_group 1;" ::: "memory");
        } else {
            asm volatile("cp.async.wait_group 0;" ::: "memory");
        }
        __syncthreads();
        uint32_t Ab = smem_base + (c & 1) * 32768;
        uint32_t Bb = Ab + 16384;
#pragma unroll
        for (int ks = 0; ks < 4; ++ks) {
            uint32_t bf[2][4];
#pragma unroll
            for (int p = 0; p < 2; ++p) {
                int nrow = warp_n * 32 + p * 16 + b_row_in;
                int kcol = ks * 16 + b_kh;
                uint32_t addr = Bb + nrow * 128 + ((uint32_t)((kcol >> 3) ^ (nrow & 7)) << 4);
                LDMX4(bf[p], addr);
            }
#pragma unroll
            for (int mi = 0; mi < 4; ++mi) {
                uint32_t af[4];
                int arow = warp_m * 64 + mi * 16 + a_row_in;
                int kcol = ks * 16 + a_kh;
                uint32_t addr = Ab + arow * 128 + ((uint32_t)((kcol >> 3) ^ (arow & 7)) << 4);
                LDMX4(af, addr);
#pragma unroll
                for (int ni = 0; ni < 4; ++ni) {
                    asm volatile(
                        "mma.sync.aligned.m16n8k16.row.col.f32.f16.f16.f32 "
                        "{%0,%1,%2,%3}, {%4,%5,%6,%7}, {%8,%9}, {%0,%1,%2,%3};"
                        : "+f"(acc[mi][ni][0]), "+f"(acc[mi][ni][1]),
                          "+f"(acc[mi][ni][2]), "+f"(acc[mi][ni][3])
                        : "r"(af[0]), "r"(af[1]), "r"(af[2]), "r"(af[3]),
                          "r"(bf[ni >> 1][(ni & 1) * 2]), "r"(bf[ni >> 1][(ni & 1) * 2 + 1]));
                }
            }
        }
        __syncthreads();
    }
#undef ISSUE_CHUNK

    // ---- epilogue: normal tile via padded smem stage (stride 136 halves) ----
    __half* stage = (__half*)smem;
#pragma unroll
    for (int mi = 0; mi < 4; ++mi)
#pragma unroll
        for (int ni = 0; ni < 4; ++ni) {
            int row = warp_m * 64 + mi * 16 + (lane >> 2);
            int col = warp_n * 32 + ni * 8 + 2 * (lane & 3);
            __half2 lo = __floats2half2_rn(acc[mi][ni][0], acc[mi][ni][1]);
            __half2 hi = __floats2half2_rn(acc[mi][ni][2], acc[mi][ni][3]);
            *(__half2*)(stage + row * 136 + col)       = lo;
            *(__half2*)(stage + (row + 8) * 136 + col) = hi;
        }
    __syncthreads();
#pragma unroll
    for (int i = tid; i < 2048; i += 256) {
        int r = i >> 4, ch = i & 15;
        uint4 v = *(uint4*)(stage + r * 136 + ch * 8);
        *(uint4*)(C + (size_t)(rowBase + r) * NPTS + colBase + ch * 8) = v;
    }

    // ---- transposed tile (Gyx / symmetric mirror), skip diagonal in sym ----
    if (!(sym && btx == bty)) {
        __syncthreads();
#pragma unroll
        for (int mi = 0; mi < 4; ++mi)
#pragma unroll
            for (int ni = 0; ni < 4; ++ni) {
                int row = warp_m * 64 + mi * 16 + (lane >> 2);
                int col = warp_n * 32 + ni * 8 + 2 * (lane & 3);
                stage[col * 136 + row]           = __float2half_rn(acc[mi][ni][0]);
                stage[(col + 1) * 136 + row]     = __float2half_rn(acc[mi][ni][1]);
                stage[col * 136 + row + 8]       = __float2half_rn(acc[mi][ni][2]);
                stage[(col + 1) * 136 + row + 8] = __float2half_rn(acc[mi][ni][3]);
            }
        __syncthreads();
#pragma unroll
        for (int i = tid; i < 2048; i += 256) {
            int r = i >> 4, ch = i & 15;
            uint4 v = *(uint4*)(stage + r * 136 + ch * 8);
            *(uint4*)(CT + (size_t)(colBase + r) * NPTS + rowBase + ch * 8) = v;
        }
    }
}

// ---------------- fused softmin over 4 (G, pot) variants ----------------
struct SMArgs {
    const __half* G[4];
    const float*  pot[4];
    const float*  oldpot[4];
    float*        out[4];
    int           avg[4];
};

__global__ void __launch_bounds__(256) softmin4(SMArgs args, float eps) {
    const int var = blockIdx.y;
    const int row = blockIdx.x;
    const int tid = threadIdx.x;
    const int lane = tid & 31, wid = tid >> 5;

    const __half* Grow = args.G[var] + (size_t)row * NPTS;
    const float*  pot  = args.pot[var];

    const float L2E = 1.4426950408889634f;
    const float c1 = L2E / eps;
    const float c0 = -c1;

    float u[32];
    float tm = -INFINITY;
#pragma unroll
    for (int it = 0; it < 4; ++it) {
        int idx = it * 256 + tid;                      // 8-half group index
        uint4 graw = ((const uint4*)Grow)[idx];
        float4 p0  = ((const float4*)pot)[2 * idx];
        float4 p1  = ((const float4*)pot)[2 * idx + 1];
        float2 g0 = __half22float2(*(const __half2*)&graw.x);
        float2 g1 = __half22float2(*(const __half2*)&graw.y);
        float2 g2 = __half22float2(*(const __half2*)&graw.z);
        float2 g3 = __half22float2(*(const __half2*)&graw.w);
        float v0 = fmaf(g0.x + p0.x, c1, c0);
        float v1 = fmaf(g0.y + p0.y, c1, c0);
        float v2 = fmaf(g1.x + p0.z, c1, c0);
        float v3 = fmaf(g1.y + p0.w, c1, c0);
        float v4 = fmaf(g2.x + p1.x, c1, c0);
        float v5 = fmaf(g2.y + p1.y, c1, c0);
        float v6 = fmaf(g3.x + p1.z, c1, c0);
        float v7 = fmaf(g3.y + p1.w, c1, c0);
        u[it * 8 + 0] = v0; u[it * 8 + 1] = v1; u[it * 8 + 2] = v2; u[it * 8 + 3] = v3;
        u[it * 8 + 4] = v4; u[it * 8 + 5] = v5; u[it * 8 + 6] = v6; u[it * 8 + 7] = v7;
        tm = fmaxf(tm, fmaxf(fmaxf(fmaxf(v0, v1), fmaxf(v2, v3)),
                             fmaxf(fmaxf(v4, v5), fmaxf(v6, v7))));
    }

#pragma unroll
    for (int off = 16; off > 0; off >>= 1)
        tm = fmaxf(tm, __shfl_xor_sync(0xffffffffu, tm, off));
    __shared__ float sred[8];
    __shared__ float ssum[8];
    if (lane == 0) sred[wid] = tm;
    __syncthreads();
    float M = sred[0];
#pragma unroll
    for (int i = 1; i < 8; ++i) M = fmaxf(M, sred[i]);

    float s = 0.0f;
    if (tm >= M - 40.0f) {
        float s0 = 0.f, s1 = 0.f, s2 = 0.f, s3 = 0.f;
#pragma unroll
        for (int i = 0; i < 32; i += 4) {
            s0 += ex2f_fast(u[i + 0] - M);
            s1 += ex2f_fast(u[i + 1] - M);
            s2 += ex2f_fast(u[i + 2] - M);
            s3 += ex2f_fast(u[i + 3] - M);
        }
        s = (s0 + s1) + (s2 + s3);
    }
#pragma unroll
    for (int off = 16; off > 0; off >>= 1)
        s += __shfl_xor_sync(0xffffffffu, s, off);
    if (lane == 0) ssum[wid] = s;
    __syncthreads();
    if (tid == 0) {
        float S = ((ssum[0] + ssum[1]) + (ssum[2] + ssum[3]))
                + ((ssum[4] + ssum[5]) + (ssum[6] + ssum[7]));
        const float LOGW = -9.010913347279288f;
        const float LN2  = 0.6931471805599453f;
        float lse = (M + log2f(S)) * LN2;
        float r = -eps * (LOGW + lse);
        if (args.avg[var]) r = 0.5f * (args.oldpot[var][row] + r);
        args.out[var][row] = r;
    }
}

// ---------------- final reduction ----------------
__global__ void final_reduce(float* __restrict__ out) {
    __shared__ float sh[1024];
    int t = threadIdx.x;
    float s = 0.0f;
    for (int i = t; i < NPTS; i += 1024)
        s += (d_ffin[i] - d_xfin[i]) + (d_gfin[i] - d_yfin[i]);
    sh[t] = s;
    __syncthreads();
    for (int off = 512; off > 0; off >>= 1) {
        if (t < off) sh[t] += sh[t + off];
        __syncthreads();
    }
    if (t == 0) out[0] = sh[0] / (float)NPTS;
}

// ---------------- host ----------------
static void* symaddr(const void* sym) {
    void* p = nullptr;
    cudaGetSymbolAddress(&p, sym);
    return p;
}

#define GEMM_SMEM 65536

extern "C" void kernel_launch(void* const* d_in, const int* in_sizes, int n_in,
                              void* d_out, int out_size) {
    const float* x1 = (const float*)d_in[0];
    const float* x2 = (const float*)d_in[1];
    const float* w  = (const float*)d_in[2];

    __half* an  = (__half*)symaddr(d_anh);
    __half* bn  = (__half*)symaddr(d_bnh);
    __half* Gxy = (__half*)symaddr(d_Gxy);
    __half* Gyx = (__half*)symaddr(d_Gyx);
    __half* Gxx = (__half*)symaddr(d_Gxx);
    __half* Gyy = (__half*)symaddr(d_Gyy);
    float* fb  = (float*)symaddr(d_f);
    float* gb  = (float*)symaddr(d_g);
    float* xb  = (float*)symaddr(d_fxx);
    float* yb  = (float*)symaddr(d_gyy);
    float* ffin = (float*)symaddr(d_ffin);
    float* gfin = (float*)symaddr(d_gfin);
    float* xfin = (float*)symaddr(d_xfin);
    float* yfin = (float*)symaddr(d_yfin);

    cudaFuncSetAttribute(gemm_mma, cudaFuncAttributeMaxDynamicSharedMemorySize, GEMM_SMEM);

    wprep_kernel<<<1, DIM>>>(w);
    rownorm_kernel<<<2 * NPTS, DIM>>>(x1, x2);
    zero_kernel<<<NPTS / 256, 256>>>();

    dim3 ggrid(NPTS / 128, NPTS / 128);
    gemm_mma<<<ggrid, 256, GEMM_SMEM>>>(an, bn, Gxy, Gyx, 0);
    gemm_mma<<<ggrid, 256, GEMM_SMEM>>>(an, an, Gxx, Gxx, 1);
    gemm_mma<<<ggrid, 256, GEMM_SMEM>>>(bn, bn, Gyy, Gyy, 1);

    const float eps_list[10] = {4.0f, 1.0f, 0.25f, 0.0625f, 0.015625f,
                                0.00390625f, 0.0025f, 0.0025f, 0.0025f, 0.0025f};
    int cur = 0;
    for (int i = 0; i < 10; ++i) {
        float eps = eps_list[i];
        int nxt = 1 - cur;
        SMArgs a;
        a.G[0] = Gxx;  a.pot[0] = xb + cur * NPTS; a.oldpot[0] = xb + cur * NPTS; a.out[0] = xb + nxt * NPTS; a.avg[0] = 1;
        a.G[1] = Gyy;  a.pot[1] = yb + cur * NPTS; a.oldpot[1] = yb + cur * NPTS; a.out[1] = yb + nxt * NPTS; a.avg[1] = 1;
        a.G[2] = Gxy;  a.pot[2] = gb + cur * NPTS; a.oldpot[2] = nullptr;         a.out[2] = fb + nxt * NPTS; a.avg[2] = 0;
        a.G[3] = Gyx;  a.pot[3] = fb + cur * NPTS; a.oldpot[3] = nullptr;         a.out[3] = gb + nxt * NPTS; a.avg[3] = 0;
        softmin4<<<dim3(NPTS, 4), 256>>>(a, eps);
        cur = nxt;
    }

    const float epsF = 0.0025f;
    {
        SMArgs a;
        a.G[0] = Gxy; a.pot[0] = gb + cur * NPTS; a.oldpot[0] = nullptr; a.out[0] = ffin; a.avg[0] = 0;
        a.G[1] = Gyx; a.pot[1] = fb + cur * NPTS; a.oldpot[1] = nullptr; a.out[1] = gfin; a.avg[1] = 0;
        a.G[2] = Gxx; a.pot[2] = xb + cur * NPTS; a.oldpot[2] = nullptr; a.out[2] = xfin; a.avg[2] = 0;
        a.G[3] = Gyy; a.pot[3] = yb + cur * NPTS; a.oldpot[3] = nullptr; a.out[3] = yfin; a.avg[3] = 0;
        softmin4<<<dim3(NPTS, 4), 256>>>(a, epsF);
    }

    final_reduce<<<1, 1024>>>((float*)d_out);
}

// round 6
// speedup vs baseline: 3.7877x; 1.0407x over previous
#include <cuda_runtime.h>
#include <cuda_fp16.h>
#include <math.h>
#include <stdint.h>

#define NPTS 8192
#define DIM 256
#define KC 64
#define NCHUNK (DIM / KC)
#define RPB 4

// ---------------- static device scratch (no allocation allowed) ----------------
__device__ float  d_wc[DIM];
__device__ __half d_anh[(size_t)NPTS * DIM];
__device__ __half d_bnh[(size_t)NPTS * DIM];
__device__ __half d_Gxy[(size_t)NPTS * NPTS];
__device__ __half d_Gyx[(size_t)NPTS * NPTS];
__device__ __half d_Gxx[(size_t)NPTS * NPTS];
__device__ __half d_Gyy[(size_t)NPTS * NPTS];
__device__ float  d_f[2][NPTS];
__device__ float  d_g[2][NPTS];
__device__ float  d_fxx[2][NPTS];
__device__ float  d_gyy[2][NPTS];
__device__ float  d_ffin[NPTS], d_gfin[NPTS], d_xfin[NPTS], d_yfin[NPTS];

__device__ __forceinline__ float ex2f_fast(float x) {
    float y; asm("ex2.approx.ftz.f32 %0, %1;" : "=f"(y) : "f"(x)); return y;
}
__device__ __forceinline__ uint32_t smem_u32(const void* p) {
    uint32_t a;
    asm("{ .reg .u64 t; cvta.to.shared.u64 t, %1; cvt.u32.u64 %0, t; }" : "=r"(a) : "l"(p));
    return a;
}
__device__ __forceinline__ void cp_async16(uint32_t dst, const void* src) {
    asm volatile("cp.async.cg.shared.global [%0], [%1], 16;" :: "r"(dst), "l"(src) : "memory");
}
#define LDMX4(r, addr)                                                          \
    asm volatile("ldmatrix.sync.aligned.m8n8.x4.shared.b16 {%0,%1,%2,%3}, [%4];" \
                 : "=r"((r)[0]), "=r"((r)[1]), "=r"((r)[2]), "=r"((r)[3])        \
                 : "r"(addr))

// ---------------- prep: clip+renormalize w ----------------
__global__ void wprep_kernel(const float* __restrict__ w) {
    __shared__ float sh[DIM];
    int t = threadIdx.x;
    float c = fminf(fmaxf(w[t], 0.0f), 2.0f);
    sh[t] = c;
    __syncthreads();
    for (int off = DIM / 2; off > 0; off >>= 1) {
        if (t < off) sh[t] += sh[t + off];
        __syncthreads();
    }
    float S = sh[0];
    d_wc[t] = c * ((float)DIM / S);
}

// ---------------- prep: row-normalize -> fp16 ----------------
__global__ void rownorm_kernel(const float* __restrict__ x1, const float* __restrict__ x2) {
    __shared__ float sh[DIM];
    int b = blockIdx.x, t = threadIdx.x;
    float v;
    if (b < NPTS) v = d_wc[t] * x1[(size_t)b * DIM + t];
    else          v = x2[(size_t)(b - NPTS) * DIM + t];
    sh[t] = v * v;
    __syncthreads();
    for (int off = DIM / 2; off > 0; off >>= 1) {
        if (t < off) sh[t] += sh[t + off];
        __syncthreads();
    }
    float inv = 1.0f / (sqrtf(sh[0]) + 1e-12f);
    __half h = __float2half_rn(v * inv);
    if (b < NPTS) d_anh[(size_t)b * DIM + t] = h;
    else          d_bnh[(size_t)(b - NPTS) * DIM + t] = h;
}

__global__ void zero_kernel() {
    int i = blockIdx.x * blockDim.x + threadIdx.x;
    if (i < NPTS) {
        d_f[0][i] = 0.0f; d_g[0][i] = 0.0f;
        d_fxx[0][i] = 0.0f; d_gyy[0][i] = 0.0f;
    }
}

// ---------------- HMMA GEMM: C = A * B^T (+ transposed output CT) ----------------
__global__ void __launch_bounds__(256, 2) gemm_mma(const __half* __restrict__ A,
                                                   const __half* __restrict__ B,
                                                   __half* __restrict__ C,
                                                   __half* __restrict__ CT,
                                                   int sym) {
    extern __shared__ char smem[];
    const int btx = blockIdx.x, bty = blockIdx.y;
    if (sym && btx > bty) return;

    const uint32_t smem_base = smem_u32(smem);
    const int tid = threadIdx.x;
    const int wid = tid >> 5, lane = tid & 31;
    const int warp_m = wid >> 2, warp_n = wid & 3;
    const int rowBase = bty * 128;
    const int colBase = btx * 128;

    const int mat = lane >> 3, rin = lane & 7;
    const int a_row_in = (mat & 1) * 8 + rin;
    const int a_kh     = (mat >> 1) * 8;
    const int b_row_in = (mat >> 1) * 8 + rin;
    const int b_kh     = (mat & 1) * 8;

    float acc[4][4][4];
#pragma unroll
    for (int mi = 0; mi < 4; ++mi)
#pragma unroll
        for (int ni = 0; ni < 4; ++ni)
#pragma unroll
            for (int q = 0; q < 4; ++q) acc[mi][ni][q] = 0.0f;

#define ISSUE_CHUNK(c, b) do {                                                  \
        const __half* Asrc_ = A + (size_t)rowBase * DIM + (c) * KC;             \
        const __half* Bsrc_ = B + (size_t)colBase * DIM + (c) * KC;             \
        uint32_t Ab_ = smem_base + (b) * 32768;                                 \
        uint32_t Bb_ = Ab_ + 16384;                                             \
        _Pragma("unroll")                                                       \
        for (int q_ = 0; q_ < 4; ++q_) {                                        \
            int i_ = q_ * 256 + tid;                                            \
            int r_ = i_ >> 3, cw_ = i_ & 7;                                     \
            uint32_t off_ = r_ * 128 + (((uint32_t)(cw_ ^ (r_ & 7))) << 4);     \
            cp_async16(Ab_ + off_, Asrc_ + (size_t)r_ * DIM + cw_ * 8);         \
            cp_async16(Bb_ + off_, Bsrc_ + (size_t)r_ * DIM + cw_ * 8);         \
        }                                                                       \
        asm volatile("cp.async.commit_group;" ::: "memory");                    \
    } while (0)

    ISSUE_CHUNK(0, 0);
#pragma unroll
    for (int c = 0; c < NCHUNK; ++c) {
        if (c + 1 < NCHUNK) {
            ISSUE_CHUNK(c + 1, (c + 1) & 1);
            asm volatile("cp.async.wait_group 1;" ::: "memory");
        } else {
            asm volatile("cp.async.wait_group 0;" ::: "memory");
        }
        __syncthreads();
        uint32_t Ab = smem_base + (c & 1) * 32768;
        uint32_t Bb = Ab + 16384;
#pragma unroll
        for (int ks = 0; ks < 4; ++ks) {
            uint32_t bf[2][4];
#pragma unroll
            for (int p = 0; p < 2; ++p) {
                int nrow = warp_n * 32 + p * 16 + b_row_in;
                int kcol = ks * 16 + b_kh;
                uint32_t addr = Bb + nrow * 128 + ((uint32_t)((kcol >> 3) ^ (nrow & 7)) << 4);
                LDMX4(bf[p], addr);
            }
#pragma unroll
            for (int mi = 0; mi < 4; ++mi) {
                uint32_t af[4];
                int arow = warp_m * 64 + mi * 16 + a_row_in;
                int kcol = ks * 16 + a_kh;
                uint32_t addr = Ab + arow * 128 + ((uint32_t)((kcol >> 3) ^ (arow & 7)) << 4);
                LDMX4(af, addr);
#pragma unroll
                for (int ni = 0; ni < 4; ++ni) {
                    asm volatile(
                        "mma.sync.aligned.m16n8k16.row.col.f32.f16.f16.f32 "
                        "{%0,%1,%2,%3}, {%4,%5,%6,%7}, {%8,%9}, {%0,%1,%2,%3};"
                        : "+f"(acc[mi][ni][0]), "+f"(acc[mi][ni][1]),
                          "+f"(acc[mi][ni][2]), "+f"(acc[mi][ni][3])
                        : "r"(af[0]), "r"(af[1]), "r"(af[2]), "r"(af[3]),
                          "r"(bf[ni >> 1][(ni & 1) * 2]), "r"(bf[ni >> 1][(ni & 1) * 2 + 1]));
                }
            }
        }
        __syncthreads();
    }
#undef ISSUE_CHUNK

    __half* stage = (__half*)smem;
#pragma unroll
    for (int mi = 0; mi < 4; ++mi)
#pragma unroll
        for (int ni = 0; ni < 4; ++ni) {
            int row = warp_m * 64 + mi * 16 + (lane >> 2);
            int col = warp_n * 32 + ni * 8 + 2 * (lane & 3);
            __half2 lo = __floats2half2_rn(acc[mi][ni][0], acc[mi][ni][1]);
            __half2 hi = __floats2half2_rn(acc[mi][ni][2], acc[mi][ni][3]);
            *(__half2*)(stage + row * 136 + col)       = lo;
            *(__half2*)(stage + (row + 8) * 136 + col) = hi;
        }
    __syncthreads();
#pragma unroll
    for (int i = tid; i < 2048; i += 256) {
        int r = i >> 4, ch = i & 15;
        uint4 v = *(uint4*)(stage + r * 136 + ch * 8);
        *(uint4*)(C + (size_t)(rowBase + r) * NPTS + colBase + ch * 8) = v;
    }

    if (!(sym && btx == bty)) {
        __syncthreads();
#pragma unroll
        for (int mi = 0; mi < 4; ++mi)
#pragma unroll
            for (int ni = 0; ni < 4; ++ni) {
                int row = warp_m * 64 + mi * 16 + (lane >> 2);
                int col = warp_n * 32 + ni * 8 + 2 * (lane & 3);
                stage[col * 136 + row]           = __float2half_rn(acc[mi][ni][0]);
                stage[(col + 1) * 136 + row]     = __float2half_rn(acc[mi][ni][1]);
                stage[col * 136 + row + 8]       = __float2half_rn(acc[mi][ni][2]);
                stage[(col + 1) * 136 + row + 8] = __float2half_rn(acc[mi][ni][3]);
            }
        __syncthreads();
#pragma unroll
        for (int i = tid; i < 2048; i += 256) {
            int r = i >> 4, ch = i & 15;
            uint4 v = *(uint4*)(stage + r * 136 + ch * 8);
            *(uint4*)(CT + (size_t)(colBase + r) * NPTS + rowBase + ch * 8) = v;
        }
    }
}

// ---------------- fused softmin: 4 variants x (RPB rows per block) ----------------
// Two-pass: pass A streams G computing only the max (pot folded into registers),
// pass B re-reads G from L2 only for warps whose local max is within 40 of M.
struct SMArgs {
    const __half* G[4];
    const float*  pot[4];
    const float*  oldpot[4];
    float*        out[4];
    int           avg[4];
};

__global__ void __launch_bounds__(256) softmin4(SMArgs args, float eps) {
    const int var  = blockIdx.y;
    const int row0 = blockIdx.x * RPB;
    const int tid  = threadIdx.x;
    const int lane = tid & 31, wid = tid >> 5;

    const float L2E = 1.4426950408889634f;
    const float c1 = L2E / eps;
    const float c0 = -c1;

    // pot folded: pp[k] = (pot_k - 1) * c1 for this thread's 32 columns
    const float* pot = args.pot[var];
    float pp[32];
#pragma unroll
    for (int it = 0; it < 4; ++it) {
        int idx = it * 256 + tid;
        float4 a = ((const float4*)pot)[2 * idx];
        float4 b = ((const float4*)pot)[2 * idx + 1];
        pp[8 * it + 0] = fmaf(a.x, c1, c0); pp[8 * it + 1] = fmaf(a.y, c1, c0);
        pp[8 * it + 2] = fmaf(a.z, c1, c0); pp[8 * it + 3] = fmaf(a.w, c1, c0);
        pp[8 * it + 4] = fmaf(b.x, c1, c0); pp[8 * it + 5] = fmaf(b.y, c1, c0);
        pp[8 * it + 6] = fmaf(b.z, c1, c0); pp[8 * it + 7] = fmaf(b.w, c1, c0);
    }

    const __half* Gbase = args.G[var];
    __shared__ float sA[RPB][8];
    __shared__ float sS[RPB][8];

    // ---- pass A: per-row max ----
    float wtm[RPB];
#pragma unroll
    for (int r = 0; r < RPB; ++r) {
        const uint4* Gr = (const uint4*)(Gbase + (size_t)(row0 + r) * NPTS);
        uint4 q[4];
        q[0] = Gr[tid]; q[1] = Gr[256 + tid]; q[2] = Gr[512 + tid]; q[3] = Gr[768 + tid];
        float tm = -INFINITY;
#pragma unroll
        for (int it = 0; it < 4; ++it) {
            float2 g0 = __half22float2(*(const __half2*)&q[it].x);
            float2 g1 = __half22float2(*(const __half2*)&q[it].y);
            float2 g2 = __half22float2(*(const __half2*)&q[it].z);
            float2 g3 = __half22float2(*(const __half2*)&q[it].w);
            float v0 = fmaf(g0.x, c1, pp[8 * it + 0]);
            float v1 = fmaf(g0.y, c1, pp[8 * it + 1]);
            float v2 = fmaf(g1.x, c1, pp[8 * it + 2]);
            float v3 = fmaf(g1.y, c1, pp[8 * it + 3]);
            float v4 = fmaf(g2.x, c1, pp[8 * it + 4]);
            float v5 = fmaf(g2.y, c1, pp[8 * it + 5]);
            float v6 = fmaf(g3.x, c1, pp[8 * it + 6]);
            float v7 = fmaf(g3.y, c1, pp[8 * it + 7]);
            tm = fmaxf(tm, fmaxf(fmaxf(fmaxf(v0, v1), fmaxf(v2, v3)),
                                 fmaxf(fmaxf(v4, v5), fmaxf(v6, v7))));
        }
#pragma unroll
        for (int off = 16; off > 0; off >>= 1)
            tm = fmaxf(tm, __shfl_xor_sync(0xffffffffu, tm, off));
        wtm[r] = tm;
        if (lane == 0) sA[r][wid] = tm;
    }
    __syncthreads();
    float M[RPB];
#pragma unroll
    for (int r = 0; r < RPB; ++r) {
        float m = sA[r][0];
#pragma unroll
        for (int i = 1; i < 8; ++i) m = fmaxf(m, sA[r][i]);
        M[r] = m;
    }

    // ---- pass B: exp-sum, only for contributing warps (G re-read hits L2) ----
#pragma unroll
    for (int r = 0; r < RPB; ++r) {
        float s = 0.0f;
        if (wtm[r] >= M[r] - 40.0f) {
            const uint4* Gr = (const uint4*)(Gbase + (size_t)(row0 + r) * NPTS);
            float Mr = M[r];
            float s0 = 0.f, s1 = 0.f, s2 = 0.f, s3 = 0.f;
#pragma unroll
            for (int it = 0; it < 4; ++it) {
                uint4 q = Gr[it * 256 + tid];
                float2 g0 = __half22float2(*(const __half2*)&q.x);
                float2 g1 = __half22float2(*(const __half2*)&q.y);
                float2 g2 = __half22float2(*(const __half2*)&q.z);
                float2 g3 = __half22float2(*(const __half2*)&q.w);
                s0 += ex2f_fast(fmaf(g0.x, c1, pp[8 * it + 0]) - Mr);
                s1 += ex2f_fast(fmaf(g0.y, c1, pp[8 * it + 1]) - Mr);
                s2 += ex2f_fast(fmaf(g1.x, c1, pp[8 * it + 2]) - Mr);
                s3 += ex2f_fast(fmaf(g1.y, c1, pp[8 * it + 3]) - Mr);
                s0 += ex2f_fast(fmaf(g2.x, c1, pp[8 * it + 4]) - Mr);
                s1 += ex2f_fast(fmaf(g2.y, c1, pp[8 * it + 5]) - Mr);
                s2 += ex2f_fast(fmaf(g3.x, c1, pp[8 * it + 6]) - Mr);
                s3 += ex2f_fast(fmaf(g3.y, c1, pp[8 * it + 7]) - Mr);
            }
            s = (s0 + s1) + (s2 + s3);
        }
#pragma unroll
        for (int off = 16; off > 0; off >>= 1)
            s += __shfl_xor_sync(0xffffffffu, s, off);
        if (lane == 0) sS[r][wid] = s;
    }
    __syncthreads();

    if (tid < RPB) {
        int r = tid;
        float S = ((sS[r][0] + sS[r][1]) + (sS[r][2] + sS[r][3]))
                + ((sS[r][4] + sS[r][5]) + (sS[r][6] + sS[r][7]));
        const float LOGW = -9.010913347279288f;   // -log(8192)
        const float LN2  = 0.6931471805599453f;
        float lse = (M[r] + log2f(S)) * LN2;
        float res = -eps * (LOGW + lse);
        if (args.avg[var]) res = 0.5f * (args.oldpot[var][row0 + r] + res);
        args.out[var][row0 + r] = res;
    }
}

// ---------------- final reduction ----------------
__global__ void final_reduce(float* __restrict__ out) {
    __shared__ float sh[1024];
    int t = threadIdx.x;
    float s = 0.0f;
    for (int i = t; i < NPTS; i += 1024)
        s += (d_ffin[i] - d_xfin[i]) + (d_gfin[i] - d_yfin[i]);
    sh[t] = s;
    __syncthreads();
    for (int off = 512; off > 0; off >>= 1) {
        if (t < off) sh[t] += sh[t + off];
        __syncthreads();
    }
    if (t == 0) out[0] = sh[0] / (float)NPTS;
}

// ---------------- host ----------------
static void* symaddr(const void* sym) {
    void* p = nullptr;
    cudaGetSymbolAddress(&p, sym);
    return p;
}

#define GEMM_SMEM 65536

extern "C" void kernel_launch(void* const* d_in, const int* in_sizes, int n_in,
                              void* d_out, int out_size) {
    const float* x1 = (const float*)d_in[0];
    const float* x2 = (const float*)d_in[1];
    const float* w  = (const float*)d_in[2];

    __half* an  = (__half*)symaddr(d_anh);
    __half* bn  = (__half*)symaddr(d_bnh);
    __half* Gxy = (__half*)symaddr(d_Gxy);
    __half* Gyx = (__half*)symaddr(d_Gyx);
    __half* Gxx = (__half*)symaddr(d_Gxx);
    __half* Gyy = (__half*)symaddr(d_Gyy);
    float* fb  = (float*)symaddr(d_f);
    float* gb  = (float*)symaddr(d_g);
    float* xb  = (float*)symaddr(d_fxx);
    float* yb  = (float*)symaddr(d_gyy);
    float* ffin = (float*)symaddr(d_ffin);
    float* gfin = (float*)symaddr(d_gfin);
    float* xfin = (float*)symaddr(d_xfin);
    float* yfin = (float*)symaddr(d_yfin);

    cudaFuncSetAttribute(gemm_mma, cudaFuncAttributeMaxDynamicSharedMemorySize, GEMM_SMEM);

    wprep_kernel<<<1, DIM>>>(w);
    rownorm_kernel<<<2 * NPTS, DIM>>>(x1, x2);
    zero_kernel<<<NPTS / 256, 256>>>();

    dim3 ggrid(NPTS / 128, NPTS / 128);
    gemm_mma<<<ggrid, 256, GEMM_SMEM>>>(an, bn, Gxy, Gyx, 0);
    gemm_mma<<<ggrid, 256, GEMM_SMEM>>>(an, an, Gxx, Gxx, 1);
    gemm_mma<<<ggrid, 256, GEMM_SMEM>>>(bn, bn, Gyy, Gyy, 1);

    const float eps_list[10] = {4.0f, 1.0f, 0.25f, 0.0625f, 0.015625f,
                                0.00390625f, 0.0025f, 0.0025f, 0.0025f, 0.0025f};
    int cur = 0;
    for (int i = 0; i < 10; ++i) {
        float eps = eps_list[i];
        int nxt = 1 - cur;
        SMArgs a;
        a.G[0] = Gxx;  a.pot[0] = xb + cur * NPTS; a.oldpot[0] = xb + cur * NPTS; a.out[0] = xb + nxt * NPTS; a.avg[0] = 1;
        a.G[1] = Gyy;  a.pot[1] = yb + cur * NPTS; a.oldpot[1] = yb + cur * NPTS; a.out[1] = yb + nxt * NPTS; a.avg[1] = 1;
        a.G[2] = Gxy;  a.pot[2] = gb + cur * NPTS; a.oldpot[2] = nullptr;         a.out[2] = fb + nxt * NPTS; a.avg[2] = 0;
        a.G[3] = Gyx;  a.pot[3] = fb + cur * NPTS; a.oldpot[3] = nullptr;         a.out[3] = gb + nxt * NPTS; a.avg[3] = 0;
        softmin4<<<dim3(NPTS / RPB, 4), 256>>>(a, eps);
        cur = nxt;
    }

    const float epsF = 0.0025f;
    {
        SMArgs a;
        a.G[0] = Gxy; a.pot[0] = gb + cur * NPTS; a.oldpot[0] = nullptr; a.out[0] = ffin; a.avg[0] = 0;
        a.G[1] = Gyx; a.pot[1] = fb + cur * NPTS; a.oldpot[1] = nullptr; a.out[1] = gfin; a.avg[1] = 0;
        a.G[2] = Gxx; a.pot[2] = xb + cur * NPTS; a.oldpot[2] = nullptr; a.out[2] = xfin; a.avg[2] = 0;
        a.G[3] = Gyy; a.pot[3] = yb + cur * NPTS; a.oldpot[3] = nullptr; a.out[3] = yfin; a.avg[3] = 0;
        softmin4<<<dim3(NPTS / RPB, 4), 256>>>(a, epsF);
    }

    final_reduce<<<1, 1024>>>((float*)d_out);
}

// round 7
// speedup vs baseline: 4.4469x; 1.1740x over previous
#include <cuda_runtime.h>
#include <cuda_fp16.h>
#include <math.h>
#include <stdint.h>

#define NPTS 8192
#define DIM 256
#define KC 64
#define NCHUNK (DIM / KC)
#define RPB 4
#define SM_SOFTMIN (RPB * 16384)   // 64 KB staged G

// ---------------- static device scratch (no allocation allowed) ----------------
__device__ float  d_wc[DIM];
__device__ __half d_anh[(size_t)NPTS * DIM];
__device__ __half d_bnh[(size_t)NPTS * DIM];
__device__ __half d_Gxy[(size_t)NPTS * NPTS];
__device__ __half d_Gyx[(size_t)NPTS * NPTS];
__device__ __half d_Gxx[(size_t)NPTS * NPTS];
__device__ __half d_Gyy[(size_t)NPTS * NPTS];
__device__ float  d_f[2][NPTS];
__device__ float  d_g[2][NPTS];
__device__ float  d_fxx[2][NPTS];
__device__ float  d_gyy[2][NPTS];
__device__ float  d_ffin[NPTS], d_gfin[NPTS], d_xfin[NPTS], d_yfin[NPTS];

__device__ __forceinline__ float ex2f_fast(float x) {
    float y; asm("ex2.approx.ftz.f32 %0, %1;" : "=f"(y) : "f"(x)); return y;
}
__device__ __forceinline__ uint32_t smem_u32(const void* p) {
    uint32_t a;
    asm("{ .reg .u64 t; cvta.to.shared.u64 t, %1; cvt.u32.u64 %0, t; }" : "=r"(a) : "l"(p));
    return a;
}
__device__ __forceinline__ void cp_async16(uint32_t dst, const void* src) {
    asm volatile("cp.async.cg.shared.global [%0], [%1], 16;" :: "r"(dst), "l"(src) : "memory");
}
#define LDMX4(r, addr)                                                          \
    asm volatile("ldmatrix.sync.aligned.m8n8.x4.shared.b16 {%0,%1,%2,%3}, [%4];" \
                 : "=r"((r)[0]), "=r"((r)[1]), "=r"((r)[2]), "=r"((r)[3])        \
                 : "r"(addr))

// ---------------- prep: clip+renormalize w ----------------
__global__ void wprep_kernel(const float* __restrict__ w) {
    __shared__ float sh[DIM];
    int t = threadIdx.x;
    float c = fminf(fmaxf(w[t], 0.0f), 2.0f);
    sh[t] = c;
    __syncthreads();
    for (int off = DIM / 2; off > 0; off >>= 1) {
        if (t < off) sh[t] += sh[t + off];
        __syncthreads();
    }
    float S = sh[0];
    d_wc[t] = c * ((float)DIM / S);
}

// ---------------- prep: row-normalize -> fp16 ----------------
__global__ void rownorm_kernel(const float* __restrict__ x1, const float* __restrict__ x2) {
    __shared__ float sh[DIM];
    int b = blockIdx.x, t = threadIdx.x;
    float v;
    if (b < NPTS) v = d_wc[t] * x1[(size_t)b * DIM + t];
    else          v = x2[(size_t)(b - NPTS) * DIM + t];
    sh[t] = v * v;
    __syncthreads();
    for (int off = DIM / 2; off > 0; off >>= 1) {
        if (t < off) sh[t] += sh[t + off];
        __syncthreads();
    }
    float inv = 1.0f / (sqrtf(sh[0]) + 1e-12f);
    __half h = __float2half_rn(v * inv);
    if (b < NPTS) d_anh[(size_t)b * DIM + t] = h;
    else          d_bnh[(size_t)(b - NPTS) * DIM + t] = h;
}

__global__ void zero_kernel() {
    int i = blockIdx.x * blockDim.x + threadIdx.x;
    if (i < NPTS) {
        d_f[0][i] = 0.0f; d_g[0][i] = 0.0f;
        d_fxx[0][i] = 0.0f; d_gyy[0][i] = 0.0f;
    }
}

// ---------------- HMMA GEMM: C = A * B^T (+ transposed output CT) ----------------
__global__ void __launch_bounds__(256, 2) gemm_mma(const __half* __restrict__ A,
                                                   const __half* __restrict__ B,
                                                   __half* __restrict__ C,
                                                   __half* __restrict__ CT,
                                                   int sym) {
    extern __shared__ char smem[];
    const int btx = blockIdx.x, bty = blockIdx.y;
    if (sym && btx > bty) return;

    const uint32_t smem_base = smem_u32(smem);
    const int tid = threadIdx.x;
    const int wid = tid >> 5, lane = tid & 31;
    const int warp_m = wid >> 2, warp_n = wid & 3;
    const int rowBase = bty * 128;
    const int colBase = btx * 128;

    const int mat = lane >> 3, rin = lane & 7;
    const int a_row_in = (mat & 1) * 8 + rin;
    const int a_kh     = (mat >> 1) * 8;
    const int b_row_in = (mat >> 1) * 8 + rin;
    const int b_kh     = (mat & 1) * 8;

    float acc[4][4][4];
#pragma unroll
    for (int mi = 0; mi < 4; ++mi)
#pragma unroll
        for (int ni = 0; ni < 4; ++ni)
#pragma unroll
            for (int q = 0; q < 4; ++q) acc[mi][ni][q] = 0.0f;

#define ISSUE_CHUNK(c, b) do {                                                  \
        const __half* Asrc_ = A + (size_t)rowBase * DIM + (c) * KC;             \
        const __half* Bsrc_ = B + (size_t)colBase * DIM + (c) * KC;             \
        uint32_t Ab_ = smem_base + (b) * 32768;                                 \
        uint32_t Bb_ = Ab_ + 16384;                                             \
        _Pragma("unroll")                                                       \
        for (int q_ = 0; q_ < 4; ++q_) {                                        \
            int i_ = q_ * 256 + tid;                                            \
            int r_ = i_ >> 3, cw_ = i_ & 7;                                     \
            uint32_t off_ = r_ * 128 + (((uint32_t)(cw_ ^ (r_ & 7))) << 4);     \
            cp_async16(Ab_ + off_, Asrc_ + (size_t)r_ * DIM + cw_ * 8);         \
            cp_async16(Bb_ + off_, Bsrc_ + (size_t)r_ * DIM + cw_ * 8);         \
        }                                                                       \
        asm volatile("cp.async.commit_group;" ::: "memory");                    \
    } while (0)

    ISSUE_CHUNK(0, 0);
#pragma unroll
    for (int c = 0; c < NCHUNK; ++c) {
        if (c + 1 < NCHUNK) {
            ISSUE_CHUNK(c + 1, (c + 1) & 1);
            asm volatile("cp.async.wait_group 1;" ::: "memory");
        } else {
            asm volatile("cp.async.wait_group 0;" ::: "memory");
        }
        __syncthreads();
        uint32_t Ab = smem_base + (c & 1) * 32768;
        uint32_t Bb = Ab + 16384;
#pragma unroll
        for (int ks = 0; ks < 4; ++ks) {
            uint32_t bf[2][4];
#pragma unroll
            for (int p = 0; p < 2; ++p) {
                int nrow = warp_n * 32 + p * 16 + b_row_in;
                int kcol = ks * 16 + b_kh;
                uint32_t addr = Bb + nrow * 128 + ((uint32_t)((kcol >> 3) ^ (nrow & 7)) << 4);
                LDMX4(bf[p], addr);
            }
#pragma unroll
            for (int mi = 0; mi < 4; ++mi) {
                uint32_t af[4];
                int arow = warp_m * 64 + mi * 16 + a_row_in;
                int kcol = ks * 16 + a_kh;
                uint32_t addr = Ab + arow * 128 + ((uint32_t)((kcol >> 3) ^ (arow & 7)) << 4);
                LDMX4(af, addr);
#pragma unroll
                for (int ni = 0; ni < 4; ++ni) {
                    asm volatile(
                        "mma.sync.aligned.m16n8k16.row.col.f32.f16.f16.f32 "
                        "{%0,%1,%2,%3}, {%4,%5,%6,%7}, {%8,%9}, {%0,%1,%2,%3};"
                        : "+f"(acc[mi][ni][0]), "+f"(acc[mi][ni][1]),
                          "+f"(acc[mi][ni][2]), "+f"(acc[mi][ni][3])
                        : "r"(af[0]), "r"(af[1]), "r"(af[2]), "r"(af[3]),
                          "r"(bf[ni >> 1][(ni & 1) * 2]), "r"(bf[ni >> 1][(ni & 1) * 2 + 1]));
                }
            }
        }
        __syncthreads();
    }
#undef ISSUE_CHUNK

    __half* stage = (__half*)smem;
#pragma unroll
    for (int mi = 0; mi < 4; ++mi)
#pragma unroll
        for (int ni = 0; ni < 4; ++ni) {
            int row = warp_m * 64 + mi * 16 + (lane >> 2);
            int col = warp_n * 32 + ni * 8 + 2 * (lane & 3);
            __half2 lo = __floats2half2_rn(acc[mi][ni][0], acc[mi][ni][1]);
            __half2 hi = __floats2half2_rn(acc[mi][ni][2], acc[mi][ni][3]);
            *(__half2*)(stage + row * 136 + col)       = lo;
            *(__half2*)(stage + (row + 8) * 136 + col) = hi;
        }
    __syncthreads();
#pragma unroll
    for (int i = tid; i < 2048; i += 256) {
        int r = i >> 4, ch = i & 15;
        uint4 v = *(uint4*)(stage + r * 136 + ch * 8);
        *(uint4*)(C + (size_t)(rowBase + r) * NPTS + colBase + ch * 8) = v;
    }

    if (!(sym && btx == bty)) {
        __syncthreads();
#pragma unroll
        for (int mi = 0; mi < 4; ++mi)
#pragma unroll
            for (int ni = 0; ni < 4; ++ni) {
                int row = warp_m * 64 + mi * 16 + (lane >> 2);
                int col = warp_n * 32 + ni * 8 + 2 * (lane & 3);
                stage[col * 136 + row]           = __float2half_rn(acc[mi][ni][0]);
                stage[(col + 1) * 136 + row]     = __float2half_rn(acc[mi][ni][1]);
                stage[col * 136 + row + 8]       = __float2half_rn(acc[mi][ni][2]);
                stage[(col + 1) * 136 + row + 8] = __float2half_rn(acc[mi][ni][3]);
            }
        __syncthreads();
#pragma unroll
        for (int i = tid; i < 2048; i += 256) {
            int r = i >> 4, ch = i & 15;
            uint4 v = *(uint4*)(stage + r * 136 + ch * 8);
            *(uint4*)(CT + (size_t)(colBase + r) * NPTS + rowBase + ch * 8) = v;
        }
    }
}

// ---------------- fused softmin: cp.async-staged, 4 variants x RPB rows ----------------
// G rows staged into SMEM via deep cp.async pipeline; pass A (max) and pass B
// (exp-sum, warp-skip) both read SMEM. Each thread reads only what it copied,
// so per-thread cp.async.wait_group ordering suffices (no barrier for data).
struct SMArgs {
    const __half* G[4];
    const float*  pot[4];
    const float*  oldpot[4];
    float*        out[4];
    int           avg[4];
};

__global__ void __launch_bounds__(256) softmin4(SMArgs args, float eps) {
    extern __shared__ char smg[];               // RPB * 16 KB
    const uint32_t smg_u = smem_u32(smg);
    const int var  = blockIdx.y;
    const int row0 = blockIdx.x * RPB;
    const int tid  = threadIdx.x;
    const int lane = tid & 31, wid = tid >> 5;

    const float L2E = 1.4426950408889634f;
    const float c1 = L2E / eps;
    const float c0 = -c1;

    // ---- issue all G copies (64 KB, 16 x 16B per thread) ----
    const __half* Gbase = args.G[var];
#pragma unroll
    for (int r = 0; r < RPB; ++r) {
        const __half* Gr = Gbase + (size_t)(row0 + r) * NPTS;
#pragma unroll
        for (int q = 0; q < 4; ++q) {
            int idx = q * 256 + tid;            // 0..1023 16B-chunks
            cp_async16(smg_u + r * 16384 + idx * 16, Gr + idx * 8);
        }
    }
    asm volatile("cp.async.commit_group;" ::: "memory");

    // ---- fold pot while copies fly: pp[k] = (pot_k - 1) * c1 ----
    const float* pot = args.pot[var];
    float pp[32];
#pragma unroll
    for (int it = 0; it < 4; ++it) {
        int idx = it * 256 + tid;
        float4 a = ((const float4*)pot)[2 * idx];
        float4 b = ((const float4*)pot)[2 * idx + 1];
        pp[8 * it + 0] = fmaf(a.x, c1, c0); pp[8 * it + 1] = fmaf(a.y, c1, c0);
        pp[8 * it + 2] = fmaf(a.z, c1, c0); pp[8 * it + 3] = fmaf(a.w, c1, c0);
        pp[8 * it + 4] = fmaf(b.x, c1, c0); pp[8 * it + 5] = fmaf(b.y, c1, c0);
        pp[8 * it + 6] = fmaf(b.z, c1, c0); pp[8 * it + 7] = fmaf(b.w, c1, c0);
    }

    asm volatile("cp.async.wait_group 0;" ::: "memory");

    __shared__ float sA[RPB][8];
    __shared__ float sS[RPB][8];

    // ---- pass A: per-row max (from SMEM) ----
    float wtm[RPB];
#pragma unroll
    for (int r = 0; r < RPB; ++r) {
        float tm = -INFINITY;
#pragma unroll
        for (int it = 0; it < 4; ++it) {
            uint4 q = *(const uint4*)(smg + r * 16384 + (it * 256 + tid) * 16);
            float2 g0 = __half22float2(*(const __half2*)&q.x);
            float2 g1 = __half22float2(*(const __half2*)&q.y);
            float2 g2 = __half22float2(*(const __half2*)&q.z);
            float2 g3 = __half22float2(*(const __half2*)&q.w);
            float v0 = fmaf(g0.x, c1, pp[8 * it + 0]);
            float v1 = fmaf(g0.y, c1, pp[8 * it + 1]);
            float v2 = fmaf(g1.x, c1, pp[8 * it + 2]);
            float v3 = fmaf(g1.y, c1, pp[8 * it + 3]);
            float v4 = fmaf(g2.x, c1, pp[8 * it + 4]);
            float v5 = fmaf(g2.y, c1, pp[8 * it + 5]);
            float v6 = fmaf(g3.x, c1, pp[8 * it + 6]);
            float v7 = fmaf(g3.y, c1, pp[8 * it + 7]);
            tm = fmaxf(tm, fmaxf(fmaxf(fmaxf(v0, v1), fmaxf(v2, v3)),
                                 fmaxf(fmaxf(v4, v5), fmaxf(v6, v7))));
        }
#pragma unroll
        for (int off = 16; off > 0; off >>= 1)
            tm = fmaxf(tm, __shfl_xor_sync(0xffffffffu, tm, off));
        wtm[r] = tm;
        if (lane == 0) sA[r][wid] = tm;
    }
    __syncthreads();
    float M[RPB];
#pragma unroll
    for (int r = 0; r < RPB; ++r) {
        float m = sA[r][0];
#pragma unroll
        for (int i = 1; i < 8; ++i) m = fmaxf(m, sA[r][i]);
        M[r] = m;
    }

    // ---- pass B: exp-sum from SMEM, only contributing warps ----
#pragma unroll
    for (int r = 0; r < RPB; ++r) {
        float s = 0.0f;
        if (wtm[r] >= M[r] - 40.0f) {
            float Mr = M[r];
            float s0 = 0.f, s1 = 0.f, s2 = 0.f, s3 = 0.f;
#pragma unroll
            for (int it = 0; it < 4; ++it) {
                uint4 q = *(const uint4*)(smg + r * 16384 + (it * 256 + tid) * 16);
                float2 g0 = __half22float2(*(const __half2*)&q.x);
                float2 g1 = __half22float2(*(const __half2*)&q.y);
                float2 g2 = __half22float2(*(const __half2*)&q.z);
                float2 g3 = __half22float2(*(const __half2*)&q.w);
                s0 += ex2f_fast(fmaf(g0.x, c1, pp[8 * it + 0]) - Mr);
                s1 += ex2f_fast(fmaf(g0.y, c1, pp[8 * it + 1]) - Mr);
                s2 += ex2f_fast(fmaf(g1.x, c1, pp[8 * it + 2]) - Mr);
                s3 += ex2f_fast(fmaf(g1.y, c1, pp[8 * it + 3]) - Mr);
                s0 += ex2f_fast(fmaf(g2.x, c1, pp[8 * it + 4]) - Mr);
                s1 += ex2f_fast(fmaf(g2.y, c1, pp[8 * it + 5]) - Mr);
                s2 += ex2f_fast(fmaf(g3.x, c1, pp[8 * it + 6]) - Mr);
                s3 += ex2f_fast(fmaf(g3.y, c1, pp[8 * it + 7]) - Mr);
            }
            s = (s0 + s1) + (s2 + s3);
        }
#pragma unroll
        for (int off = 16; off > 0; off >>= 1)
            s += __shfl_xor_sync(0xffffffffu, s, off);
        if (lane == 0) sS[r][wid] = s;
    }
    __syncthreads();

    if (tid < RPB) {
        int r = tid;
        float S = ((sS[r][0] + sS[r][1]) + (sS[r][2] + sS[r][3]))
                + ((sS[r][4] + sS[r][5]) + (sS[r][6] + sS[r][7]));
        const float LOGW = -9.010913347279288f;   // -log(8192)
        const float LN2  = 0.6931471805599453f;
        float lse = (M[r] + log2f(S)) * LN2;
        float res = -eps * (LOGW + lse);
        if (args.avg[var]) res = 0.5f * (args.oldpot[var][row0 + r] + res);
        args.out[var][row0 + r] = res;
    }
}

// ---------------- final reduction ----------------
__global__ void final_reduce(float* __restrict__ out) {
    __shared__ float sh[1024];
    int t = threadIdx.x;
    float s = 0.0f;
    for (int i = t; i < NPTS; i += 1024)
        s += (d_ffin[i] - d_xfin[i]) + (d_gfin[i] - d_yfin[i]);
    sh[t] = s;
    __syncthreads();
    for (int off = 512; off > 0; off >>= 1) {
        if (t < off) sh[t] += sh[t + off];
        __syncthreads();
    }
    if (t == 0) out[0] = sh[0] / (float)NPTS;
}

// ---------------- host ----------------
static void* symaddr(const void* sym) {
    void* p = nullptr;
    cudaGetSymbolAddress(&p, sym);
    return p;
}

#define GEMM_SMEM 65536

extern "C" void kernel_launch(void* const* d_in, const int* in_sizes, int n_in,
                              void* d_out, int out_size) {
    const float* x1 = (const float*)d_in[0];
    const float* x2 = (const float*)d_in[1];
    const float* w  = (const float*)d_in[2];

    __half* an  = (__half*)symaddr(d_anh);
    __half* bn  = (__half*)symaddr(d_bnh);
    __half* Gxy = (__half*)symaddr(d_Gxy);
    __half* Gyx = (__half*)symaddr(d_Gyx);
    __half* Gxx = (__half*)symaddr(d_Gxx);
    __half* Gyy = (__half*)symaddr(d_Gyy);
    float* fb  = (float*)symaddr(d_f);
    float* gb  = (float*)symaddr(d_g);
    float* xb  = (float*)symaddr(d_fxx);
    float* yb  = (float*)symaddr(d_gyy);
    float* ffin = (float*)symaddr(d_ffin);
    float* gfin = (float*)symaddr(d_gfin);
    float* xfin = (float*)symaddr(d_xfin);
    float* yfin = (float*)symaddr(d_yfin);

    cudaFuncSetAttribute(gemm_mma, cudaFuncAttributeMaxDynamicSharedMemorySize, GEMM_SMEM);
    cudaFuncSetAttribute(softmin4, cudaFuncAttributeMaxDynamicSharedMemorySize, SM_SOFTMIN);

    wprep_kernel<<<1, DIM>>>(w);
    rownorm_kernel<<<2 * NPTS, DIM>>>(x1, x2);
    zero_kernel<<<NPTS / 256, 256>>>();

    dim3 ggrid(NPTS / 128, NPTS / 128);
    gemm_mma<<<ggrid, 256, GEMM_SMEM>>>(an, bn, Gxy, Gyx, 0);
    gemm_mma<<<ggrid, 256, GEMM_SMEM>>>(an, an, Gxx, Gxx, 1);
    gemm_mma<<<ggrid, 256, GEMM_SMEM>>>(bn, bn, Gyy, Gyy, 1);

    const float eps_list[10] = {4.0f, 1.0f, 0.25f, 0.0625f, 0.015625f,
                                0.00390625f, 0.0025f, 0.0025f, 0.0025f, 0.0025f};
    int cur = 0;
    for (int i = 0; i < 10; ++i) {
        float eps = eps_list[i];
        int nxt = 1 - cur;
        SMArgs a;
        a.G[0] = Gxx;  a.pot[0] = xb + cur * NPTS; a.oldpot[0] = xb + cur * NPTS; a.out[0] = xb + nxt * NPTS; a.avg[0] = 1;
        a.G[1] = Gyy;  a.pot[1] = yb + cur * NPTS; a.oldpot[1] = yb + cur * NPTS; a.out[1] = yb + nxt * NPTS; a.avg[1] = 1;
        a.G[2] = Gxy;  a.pot[2] = gb + cur * NPTS; a.oldpot[2] = nullptr;         a.out[2] = fb + nxt * NPTS; a.avg[2] = 0;
        a.G[3] = Gyx;  a.pot[3] = fb + cur * NPTS; a.oldpot[3] = nullptr;         a.out[3] = gb + nxt * NPTS; a.avg[3] = 0;
        softmin4<<<dim3(NPTS / RPB, 4), 256, SM_SOFTMIN>>>(a, eps);
        cur = nxt;
    }

    const float epsF = 0.0025f;
    {
        SMArgs a;
        a.G[0] = Gxy; a.pot[0] = gb + cur * NPTS; a.oldpot[0] = nullptr; a.out[0] = ffin; a.avg[0] = 0;
        a.G[1] = Gyx; a.pot[1] = fb + cur * NPTS; a.oldpot[1] = nullptr; a.out[1] = gfin; a.avg[1] = 0;
        a.G[2] = Gxx; a.pot[2] = xb + cur * NPTS; a.oldpot[2] = nullptr; a.out[2] = xfin; a.avg[2] = 0;
        a.G[3] = Gyy; a.pot[3] = yb + cur * NPTS; a.oldpot[3] = nullptr; a.out[3] = yfin; a.avg[3] = 0;
        softmin4<<<dim3(NPTS / RPB, 4), 256, SM_SOFTMIN>>>(a, epsF);
    }

    final_reduce<<<1, 1024>>>((float*)d_out);
}